// round 4
// baseline (speedup 1.0000x reference)
#include <cuda_runtime.h>
#include <math.h>
#include <stdint.h>

#define NMAX   50000
#define EMAX   600000
#define HIDW   256
#define OUTW   352
#define OUTT   349
#define MAXNTOT 272

// ---------------- scratch (device globals) ----------------------------------
__device__ int   g_deg[NMAX];
__device__ float g_dinv[NMAX];
__device__ int   g_off[NMAX + 1];
__device__ int   g_cur[NMAX];
__device__ int   g_adj[EMAX];
__device__ int   g_bsum[256];
__device__ float g_lin[(size_t)NMAX * MAXNTOT];
__device__ float g_hA[(size_t)NMAX * HIDW];
__device__ float g_hB[(size_t)NMAX * HIDW];

// ---------------- CSR build --------------------------------------------------
__global__ void k_zero(int n) {
    int i = blockIdx.x * blockDim.x + threadIdx.x;
    if (i < n) g_deg[i] = 0;
}

__global__ void k_deg(const int* __restrict__ row, int e) {
    int i = blockIdx.x * blockDim.x + threadIdx.x;
    if (i < e) atomicAdd(&g_deg[row[i]], 1);
}

__global__ void k_dinv(int n) {
    int i = blockIdx.x * blockDim.x + threadIdx.x;
    if (i < n) {
        int d = g_deg[i];
        g_dinv[i] = (d > 0) ? rsqrtf((float)d) : 0.0f;
    }
}

__global__ void k_scan1(int n) {
    __shared__ int sh[256];
    int t = threadIdx.x;
    int i = blockIdx.x * 256 + t;
    sh[t] = (i < n) ? g_deg[i] : 0;
    __syncthreads();
#pragma unroll
    for (int s = 128; s; s >>= 1) {
        if (t < s) sh[t] += sh[t + s];
        __syncthreads();
    }
    if (t == 0) g_bsum[blockIdx.x] = sh[0];
}

__global__ void k_scan2(int nb) {
    __shared__ int sh[256];
    int t = threadIdx.x;
    int v = (t < nb) ? g_bsum[t] : 0;
    sh[t] = v;
    __syncthreads();
#pragma unroll
    for (int d = 1; d < 256; d <<= 1) {
        int u = (t >= d) ? sh[t - d] : 0;
        __syncthreads();
        sh[t] += u;
        __syncthreads();
    }
    if (t < nb) g_bsum[t] = sh[t] - v;
}

__global__ void k_scan3(int n, int total) {
    __shared__ int sh[256];
    int t = threadIdx.x;
    int i = blockIdx.x * 256 + t;
    int v = (i < n) ? g_deg[i] : 0;
    sh[t] = v;
    __syncthreads();
#pragma unroll
    for (int d = 1; d < 256; d <<= 1) {
        int u = (t >= d) ? sh[t - d] : 0;
        __syncthreads();
        sh[t] += u;
        __syncthreads();
    }
    int excl = sh[t] - v + g_bsum[blockIdx.x];
    if (i < n) { g_off[i] = excl; g_cur[i] = excl; }
    if (blockIdx.x == 0 && t == 0) g_off[n] = total;
}

__global__ void k_scatter(const int* __restrict__ row, const int* __restrict__ col, int e) {
    int i = blockIdx.x * blockDim.x + threadIdx.x;
    if (i < e) {
        int r = row[i];
        int p = atomicAdd(&g_cur[r], 1);
        g_adj[p] = col[i];
    }
}

// ---------------- tf32 tensor-core GEMM (fragment-packed smem) ----------------
__device__ __forceinline__ uint32_t f2tf(float x) {
    uint32_t y;
    asm("cvt.rna.tf32.f32 %0, %1;" : "=r"(y) : "f"(x));
    return y;
}

__device__ __forceinline__ float4 ld4(const float* p) {
    return p ? __ldg(reinterpret_cast<const float4*>(p))
             : make_float4(0.f, 0.f, 0.f, 0.f);
}

__device__ __forceinline__ void mma8(float* c, const uint32_t* a, const uint32_t* b) {
    asm volatile(
        "mma.sync.aligned.m16n8k8.row.col.f32.tf32.tf32.f32 "
        "{%0,%1,%2,%3}, {%4,%5,%6,%7}, {%8,%9}, {%0,%1,%2,%3};"
        : "+f"(c[0]), "+f"(c[1]), "+f"(c[2]), "+f"(c[3])
        : "r"(a[0]), "r"(a[1]), "r"(a[2]), "r"(a[3]), "r"(b[0]), "r"(b[1]));
}

// A fragment smem: [buf][mtile 8][ks 2][off 128], off = lane*4+reg, swizzled.
// B fragment smem: [buf][ntile 2NT][ks 2][off 64], off = lane*2+reg, swizzled by nt.
template<int NT>
__global__ __launch_bounds__(256)
void k_gemm_t(const float* __restrict__ A, const float* __restrict__ Wb,
              const float* __restrict__ Wc, const float* __restrict__ bc,
              float* __restrict__ C, int M, int K, int NBF, int Ntot)
{
    constexpr int BN     = 16 * NT;
    constexpr int NB4    = BN / 4;
    constexpr int TB4    = 16 * NB4;
    constexpr int NTILES = BN / 8;

    __shared__ uint32_t As[2][8][2][128];
    __shared__ uint32_t Bs[2][NTILES][2][64];

    const int tid  = threadIdx.x;
    const int bm   = blockIdx.y * 128;
    const int bn   = blockIdx.x * BN;
    const int w    = tid >> 5, lane = tid & 31;
    const int wm   = w & 3,   wn   = w >> 2;
    const int g    = lane >> 2, t4 = lane & 3;
    const int cw   = Ntot - NBF;

    // ---- A prefetch lanes ----
    int am[2], ak[2];
    const float* pa[2];
#pragma unroll
    for (int j = 0; j < 2; j++) {
        int id = tid + j * 256;
        am[j] = id >> 2;
        ak[j] = (id & 3) * 4;
        int gm = bm + am[j];
        pa[j] = (gm < M) ? A + (size_t)gm * K + ak[j] : nullptr;
    }

    // ---- B prefetch lanes ----
    int bkk[2], bnq[2];
    bool bval[2];
    const float* pb[2];
    int bpit[2];
#pragma unroll
    for (int j = 0; j < 2; j++) {
        int id = tid + j * 256;
        bval[j] = (id < TB4);
        int kk = bval[j] ? id / NB4 : 0;
        int nq = bval[j] ? id % NB4 : 0;
        bkk[j] = kk; bnq[j] = nq;
        int gn4 = bn + nq * 4;
        pb[j] = nullptr; bpit[j] = 0;
        if (bval[j]) {
            if (gn4 < NBF)       { pb[j] = Wb + (size_t)kk * NBF + gn4;         bpit[j] = NBF; }
            else if (gn4 < Ntot) { pb[j] = Wc + (size_t)kk * cw  + (gn4 - NBF); bpit[j] = cw;  }
        }
    }

    float acc[2][NT][4];
#pragma unroll
    for (int i = 0; i < 2; i++)
#pragma unroll
        for (int j = 0; j < NT; j++)
#pragma unroll
            for (int r = 0; r < 4; r++) acc[i][j][r] = 0.0f;

    float4 ra[2], rb[2];
#pragma unroll
    for (int j = 0; j < 2; j++) { ra[j] = ld4(pa[j]); rb[j] = ld4(pb[j]); }

    // fragment-store helpers (in-lined twice below)
#define STORE_TILE(BUF)                                                          \
    do {                                                                         \
        _Pragma("unroll")                                                        \
        for (int j = 0; j < 2; j++) {                                            \
            int mt = am[j] >> 4;                                                 \
            int ih = (am[j] >> 3) & 1;                                           \
            int g8 = am[j] & 7;                                                  \
            int ks = ak[j] >> 3;                                                 \
            int kh = (ak[j] >> 2) & 1;                                           \
            int rg = ih + 2 * kh;                                                \
            float av[4] = { ra[j].x, ra[j].y, ra[j].z, ra[j].w };                \
            _Pragma("unroll")                                                    \
            for (int jj = 0; jj < 4; jj++) {                                     \
                int off = g8 * 16 + jj * 4 + rg;                                 \
                int phy = off ^ ((off >> 2) & 0xC);                              \
                As[BUF][mt][ks][phy] = f2tf(av[jj]);                             \
            }                                                                    \
            if (bval[j]) {                                                       \
                int kk = bkk[j];                                                 \
                int ksb = kk >> 3, t4b = kk & 3, khb = (kk >> 2) & 1;            \
                int nt = bnq[j] >> 1;                                            \
                float bv[4] = { rb[j].x, rb[j].y, rb[j].z, rb[j].w };            \
                _Pragma("unroll")                                                \
                for (int jj = 0; jj < 4; jj++) {                                 \
                    int gc = (bnq[j] & 1) * 4 + jj;                              \
                    int off = gc * 8 + t4b * 2 + khb;                            \
                    int phy = off ^ ((nt & 3) << 3);                             \
                    Bs[BUF][nt][ksb][phy] = f2tf(bv[jj]);                        \
                }                                                                \
            }                                                                    \
        }                                                                        \
    } while (0)

    int buf = 0;
    STORE_TILE(0);
    __syncthreads();

    const int aphy  = (lane * 4) ^ (lane & 0xC);
    const int kiter = K >> 4;

    for (int it = 1; it <= kiter; it++) {
        if (it < kiter) {
#pragma unroll
            for (int j = 0; j < 2; j++) {
                if (pa[j]) pa[j] += 16;
                if (pb[j]) pb[j] += (size_t)bpit[j] * 16;
                ra[j] = ld4(pa[j]);
                rb[j] = ld4(pb[j]);
            }
        }
#pragma unroll
        for (int ks = 0; ks < 2; ks++) {
            uint4 af0 = *reinterpret_cast<const uint4*>(&As[buf][wm * 2 + 0][ks][aphy]);
            uint4 af1 = *reinterpret_cast<const uint4*>(&As[buf][wm * 2 + 1][ks][aphy]);
            uint2 bf[NT];
#pragma unroll
            for (int j = 0; j < NT; j++) {
                int nt = wn * NT + j;
                bf[j] = *reinterpret_cast<const uint2*>(
                    &Bs[buf][nt][ks][(lane * 2) ^ ((nt & 3) << 3)]);
            }
#pragma unroll
            for (int j = 0; j < NT; j++) {
                mma8(acc[0][j], &af0.x, &bf[j].x);
                mma8(acc[1][j], &af1.x, &bf[j].x);
            }
        }
        if (it < kiter) {
            int nb = buf ^ 1;
            if (nb) STORE_TILE(1); else STORE_TILE(0);
            __syncthreads();
            buf = nb;
        }
    }
#undef STORE_TILE

    // ---- epilogue ----
    const int rm0 = wm * 32;
    const int cn0 = wn * NT * 8;
#pragma unroll
    for (int i = 0; i < 2; i++) {
        int r0 = bm + rm0 + i * 16 + g;
#pragma unroll
        for (int j = 0; j < NT; j++) {
            int col = bn + cn0 + j * 8 + 2 * t4;
            if (col >= Ntot) continue;
            float b0 = 0.f, b1 = 0.f;
            if (col >= NBF) { b0 = bc[col - NBF]; b1 = bc[col - NBF + 1]; }
            if (r0 < M) {
                float2 v = make_float2(acc[i][j][0] + b0, acc[i][j][1] + b1);
                *reinterpret_cast<float2*>(&C[(size_t)r0 * Ntot + col]) = v;
            }
            if (r0 + 8 < M) {
                float2 v = make_float2(acc[i][j][2] + b0, acc[i][j][3] + b1);
                *reinterpret_cast<float2*>(&C[(size_t)(r0 + 8) * Ntot + col]) = v;
            }
        }
    }
}

// ---------------- fused aggregation + combine + bias (+relu / +log_softmax) --
template<int NBF, int F, bool RELU, bool LSM>
__global__ __launch_bounds__(256)
void k_agg(const float* __restrict__ lin, int stride,
           const float* __restrict__ bias,
           float* __restrict__ out, int n)
{
    constexpr int HF  = 8 * F;
    constexpr int NI  = HF / 32;
    constexpr int C4  = (NBF + 127) / 128;
    constexpr int NF4 = NBF / 4;
    __shared__ float agg_s[8][3 * NBF];
    __shared__ float comb_s[8][96];

    int gw   = (blockIdx.x * 256 + threadIdx.x) >> 5;
    int lane = threadIdx.x & 31;
    int lw   = threadIdx.x >> 5;
    if (gw >= n) return;

    int s = g_off[gw], e = g_off[gw + 1];
    int deg = e - s;

    float4 vsym[C4], vsum[C4], vmax[C4];
#pragma unroll
    for (int q = 0; q < C4; q++) {
        vsym[q] = make_float4(0.f, 0.f, 0.f, 0.f);
        vsum[q] = make_float4(0.f, 0.f, 0.f, 0.f);
        vmax[q] = make_float4(-INFINITY, -INFINITY, -INFINITY, -INFINITY);
    }

    int t = s;
    for (; t + 4 <= e; t += 4) {
        int c0 = g_adj[t], c1 = g_adj[t + 1], c2 = g_adj[t + 2], c3 = g_adj[t + 3];
        float d0 = g_dinv[c0], d1 = g_dinv[c1], d2 = g_dinv[c2], d3 = g_dinv[c3];
        const float4* s0 = reinterpret_cast<const float4*>(lin + (size_t)c0 * stride);
        const float4* s1 = reinterpret_cast<const float4*>(lin + (size_t)c1 * stride);
        const float4* s2 = reinterpret_cast<const float4*>(lin + (size_t)c2 * stride);
        const float4* s3 = reinterpret_cast<const float4*>(lin + (size_t)c3 * stride);
#pragma unroll
        for (int q = 0; q < C4; q++) {
            int i4 = lane + q * 32;
            if (C4 > 1 && i4 >= NF4) break;
            float4 v0 = s0[i4], v1 = s1[i4], v2 = s2[i4], v3 = s3[i4];
            vsym[q].x += (d0 * v0.x + d1 * v1.x) + (d2 * v2.x + d3 * v3.x);
            vsym[q].y += (d0 * v0.y + d1 * v1.y) + (d2 * v2.y + d3 * v3.y);
            vsym[q].z += (d0 * v0.z + d1 * v1.z) + (d2 * v2.z + d3 * v3.z);
            vsym[q].w += (d0 * v0.w + d1 * v1.w) + (d2 * v2.w + d3 * v3.w);
            vsum[q].x += (v0.x + v1.x) + (v2.x + v3.x);
            vsum[q].y += (v0.y + v1.y) + (v2.y + v3.y);
            vsum[q].z += (v0.z + v1.z) + (v2.z + v3.z);
            vsum[q].w += (v0.w + v1.w) + (v2.w + v3.w);
            vmax[q].x = fmaxf(vmax[q].x, fmaxf(fmaxf(v0.x, v1.x), fmaxf(v2.x, v3.x)));
            vmax[q].y = fmaxf(vmax[q].y, fmaxf(fmaxf(v0.y, v1.y), fmaxf(v2.y, v3.y)));
            vmax[q].z = fmaxf(vmax[q].z, fmaxf(fmaxf(v0.z, v1.z), fmaxf(v2.z, v3.z)));
            vmax[q].w = fmaxf(vmax[q].w, fmaxf(fmaxf(v0.w, v1.w), fmaxf(v2.w, v3.w)));
        }
    }
    for (; t < e; t++) {
        int c0 = g_adj[t];
        float d0 = g_dinv[c0];
        const float4* s0 = reinterpret_cast<const float4*>(lin + (size_t)c0 * stride);
#pragma unroll
        for (int q = 0; q < C4; q++) {
            int i4 = lane + q * 32;
            if (C4 > 1 && i4 >= NF4) break;
            float4 v0 = s0[i4];
            vsym[q].x += d0 * v0.x; vsym[q].y += d0 * v0.y;
            vsym[q].z += d0 * v0.z; vsym[q].w += d0 * v0.w;
            vsum[q].x += v0.x; vsum[q].y += v0.y;
            vsum[q].z += v0.z; vsum[q].w += v0.w;
            vmax[q].x = fmaxf(vmax[q].x, v0.x); vmax[q].y = fmaxf(vmax[q].y, v0.y);
            vmax[q].z = fmaxf(vmax[q].z, v0.z); vmax[q].w = fmaxf(vmax[q].w, v0.w);
        }
    }

    float dn   = g_dinv[gw];
    float invd = (deg > 0) ? (1.0f / (float)deg) : 0.0f;

    float4* arow0 = reinterpret_cast<float4*>(&agg_s[lw][0]);
    float4* arow1 = reinterpret_cast<float4*>(&agg_s[lw][NBF]);
    float4* arow2 = reinterpret_cast<float4*>(&agg_s[lw][2 * NBF]);
#pragma unroll
    for (int q = 0; q < C4; q++) {
        int i4 = lane + q * 32;
        if (C4 > 1 && i4 >= NF4) break;
        float4 sy = vsym[q];
        sy.x *= dn; sy.y *= dn; sy.z *= dn; sy.w *= dn;
        float4 me = vsum[q];
        me.x *= invd; me.y *= invd; me.z *= invd; me.w *= invd;
        float4 mx = vmax[q];
        if (deg == 0) mx = make_float4(0.f, 0.f, 0.f, 0.f);
        arow0[i4] = sy;
        arow1[i4] = me;
        arow2[i4] = mx;
    }

    const float* comb = lin + (size_t)gw * stride + NBF;
    comb_s[lw][lane]      = comb[lane];
    comb_s[lw][lane + 32] = comb[lane + 32];
    comb_s[lw][lane + 64] = comb[lane + 64];
    __syncwarp();

    float vals[NI];
#pragma unroll
    for (int i = 0; i < NI; i++) {
        int c = lane + i * 32;
        int h = c / F, f = c % F;
        float v = bias[c];
        const float* cb = &comb_s[lw][h * 12];
        const float* ag = &agg_s[lw][0];
#pragma unroll
        for (int k = 0; k < 12; k++) v = fmaf(cb[k], ag[k * F + f], v);
        if (RELU) v = fmaxf(v, 0.0f);
        vals[i] = v;
    }

    if (!LSM) {
#pragma unroll
        for (int i = 0; i < NI; i++)
            out[(size_t)gw * HF + lane + i * 32] = vals[i];
    } else {
        // fused log_softmax over first OUTT columns
        float m = -INFINITY;
#pragma unroll
        for (int i = 0; i < NI; i++) {
            int c = lane + i * 32;
            m = fmaxf(m, (c < OUTT) ? vals[i] : -INFINITY);
        }
#pragma unroll
        for (int o = 16; o; o >>= 1) m = fmaxf(m, __shfl_xor_sync(0xffffffffu, m, o));
        float sum = 0.0f;
#pragma unroll
        for (int i = 0; i < NI; i++) {
            int c = lane + i * 32;
            if (c < OUTT) sum += expf(vals[i] - m);
        }
#pragma unroll
        for (int o = 16; o; o >>= 1) sum += __shfl_xor_sync(0xffffffffu, sum, o);
        float l = m + logf(sum);
#pragma unroll
        for (int i = 0; i < NI; i++) {
            int c = lane + i * 32;
            if (c < OUTT) out[(size_t)gw * OUTT + c] = vals[i] - l;
        }
    }
}

// ---------------- launch --------------------------------------------------------
extern "C" void kernel_launch(void* const* d_in, const int* in_sizes, int n_in,
                              void* d_out, int out_size)
{
    const float* x   = (const float*)d_in[0];
    const int*   ei  = (const int*)d_in[1];
    int N = in_sizes[0] / 128;
    int E = in_sizes[1] / 2;
    if (N > NMAX) N = NMAX;
    if (E > EMAX) E = EMAX;
    const int* row = ei;
    const int* col = ei + E;

    const float* Wb0 = (const float*)d_in[2];
    const float* Wc0 = (const float*)d_in[3];
    const float* bc0 = (const float*)d_in[4];
    const float* b0  = (const float*)d_in[5];
    const float* Wb1 = (const float*)d_in[6];
    const float* Wc1 = (const float*)d_in[7];
    const float* bc1 = (const float*)d_in[8];
    const float* b1  = (const float*)d_in[9];
    const float* Wb2 = (const float*)d_in[10];
    const float* Wc2 = (const float*)d_in[11];
    const float* bc2 = (const float*)d_in[12];
    const float* b2  = (const float*)d_in[13];

    float* lin; float* hA; float* hB;
    cudaGetSymbolAddress((void**)&lin, g_lin);
    cudaGetSymbolAddress((void**)&hA,  g_hA);
    cudaGetSymbolAddress((void**)&hB,  g_hB);

    const int T  = 256;
    const int gy = (N + 127) / 128;
    const int ab = (N + 7) / 8;
    const int sb = (N + 255) / 256;

    // CSR build interleaved with layer-0 GEMM (independent of CSR)
    k_zero   <<<(N + T - 1) / T, T>>>(N);
    k_deg    <<<(E + T - 1) / T, T>>>(row, E);
    k_dinv   <<<(N + T - 1) / T, T>>>(N);
    k_gemm_t<7><<<dim3(2, gy), 256>>>(x, Wb0, Wc0, bc0, lin, N, 128, 128, 224);
    k_scan1  <<<sb, 256>>>(N);
    k_scan2  <<<1, 256>>>(sb);
    k_scan3  <<<sb, 256>>>(N, E);
    k_scatter<<<(E + T - 1) / T, T>>>(row, col, E);

    k_agg<128, 32, true, false><<<ab, 256>>>(lin, 224, b0, hA, N);

    k_gemm_t<7><<<dim3(2, gy), 256>>>(hA, Wb1, Wc1, bc1, lin, N, 256, 128, 224);
    k_agg<128, 32, true, false><<<ab, 256>>>(lin, 224, b1, hB, N);

    k_gemm_t<6><<<dim3(3, gy), 256>>>(hB, Wb2, Wc2, bc2, lin, N, 256, 176, 272);
    // layer-2 aggregation fused with log_softmax, writes d_out directly
    k_agg<176, 44, false, true><<<ab, 256>>>(lin, 272, b2, (float*)d_out, N);
}

// round 5
// speedup vs baseline: 1.1857x; 1.1857x over previous
#include <cuda_runtime.h>
#include <cuda_fp16.h>
#include <math.h>
#include <stdint.h>

#define NMAX   50000
#define EMAX   600000
#define HIDW   256
#define OUTW   352
#define OUTT   349
#define MAXNTOT 272

// ---------------- scratch (device globals) ----------------------------------
__device__ int   g_deg[NMAX];
__device__ float g_dinv[NMAX];
__device__ int   g_off[NMAX + 1];
__device__ int   g_cur[NMAX];
__device__ int   g_adj[EMAX];
__device__ int   g_bsum[256];
__device__ float g_lin[(size_t)NMAX * MAXNTOT];
__device__ float g_hA[(size_t)NMAX * HIDW];
__device__ float g_hB[(size_t)NMAX * HIDW];

// ---------------- CSR build --------------------------------------------------
__global__ void k_zero(int n) {
    int i = blockIdx.x * blockDim.x + threadIdx.x;
    if (i < n) g_deg[i] = 0;
}

__global__ void k_deg(const int* __restrict__ row, int e) {
    int i = blockIdx.x * blockDim.x + threadIdx.x;
    if (i < e) atomicAdd(&g_deg[row[i]], 1);
}

__global__ void k_dinv(int n) {
    int i = blockIdx.x * blockDim.x + threadIdx.x;
    if (i < n) {
        int d = g_deg[i];
        g_dinv[i] = (d > 0) ? rsqrtf((float)d) : 0.0f;
    }
}

__global__ void k_scan1(int n) {
    __shared__ int sh[256];
    int t = threadIdx.x;
    int i = blockIdx.x * 256 + t;
    sh[t] = (i < n) ? g_deg[i] : 0;
    __syncthreads();
#pragma unroll
    for (int s = 128; s; s >>= 1) {
        if (t < s) sh[t] += sh[t + s];
        __syncthreads();
    }
    if (t == 0) g_bsum[blockIdx.x] = sh[0];
}

__global__ void k_scan2(int nb) {
    __shared__ int sh[256];
    int t = threadIdx.x;
    int v = (t < nb) ? g_bsum[t] : 0;
    sh[t] = v;
    __syncthreads();
#pragma unroll
    for (int d = 1; d < 256; d <<= 1) {
        int u = (t >= d) ? sh[t - d] : 0;
        __syncthreads();
        sh[t] += u;
        __syncthreads();
    }
    if (t < nb) g_bsum[t] = sh[t] - v;
}

__global__ void k_scan3(int n, int total) {
    __shared__ int sh[256];
    int t = threadIdx.x;
    int i = blockIdx.x * 256 + t;
    int v = (i < n) ? g_deg[i] : 0;
    sh[t] = v;
    __syncthreads();
#pragma unroll
    for (int d = 1; d < 256; d <<= 1) {
        int u = (t >= d) ? sh[t - d] : 0;
        __syncthreads();
        sh[t] += u;
        __syncthreads();
    }
    int excl = sh[t] - v + g_bsum[blockIdx.x];
    if (i < n) { g_off[i] = excl; g_cur[i] = excl; }
    if (blockIdx.x == 0 && t == 0) g_off[n] = total;
}

__global__ void k_scatter(const int* __restrict__ row, const int* __restrict__ col, int e) {
    int i = blockIdx.x * blockDim.x + threadIdx.x;
    if (i < e) {
        int r = row[i];
        int p = atomicAdd(&g_cur[r], 1);
        g_adj[p] = col[i];
    }
}

// ---------------- fp16 tensor-core GEMM --------------------------------------
// C[M,Ntot] = A[M,K] @ [Wb|Wc] + [0|bc].  BM=128, BN=16*NT, BK=16.
// 8 warps (4m x 2n); warp does 2 x NT m16n8k16 fp16 MMAs (f32 accum) per tile.
__device__ __forceinline__ uint32_t pk(float a, float b) {
    __half2 h = __floats2half2_rn(a, b);
    return *reinterpret_cast<uint32_t*>(&h);
}

__device__ __forceinline__ float4 ld4(const float* p) {
    return p ? __ldg(reinterpret_cast<const float4*>(p))
             : make_float4(0.f, 0.f, 0.f, 0.f);
}

__device__ __forceinline__ void mma16(float* c, const uint32_t* a, const uint32_t* b) {
    asm volatile(
        "mma.sync.aligned.m16n8k16.row.col.f32.f16.f16.f32 "
        "{%0,%1,%2,%3}, {%4,%5,%6,%7}, {%8,%9}, {%0,%1,%2,%3};"
        : "+f"(c[0]), "+f"(c[1]), "+f"(c[2]), "+f"(c[3])
        : "r"(a[0]), "r"(a[1]), "r"(a[2]), "r"(a[3]), "r"(b[0]), "r"(b[1]));
}

// A smem: [buf][row 128][k2 8] pitch 12 (conflict-free frag loads).
// B smem: [buf][k2 8][col BN] pitch BP == 8 (mod 32) (conflict-free frag loads).
template<int NT>
__global__ __launch_bounds__(256)
void k_gemm_h(const float* __restrict__ A, const float* __restrict__ Wb,
              const float* __restrict__ Wc, const float* __restrict__ bc,
              float* __restrict__ C, int M, int K, int NBF, int Ntot)
{
    constexpr int BN  = 16 * NT;
    constexpr int NB4 = BN / 4;
    constexpr int TB2 = 8 * NB4;                           // paired B slots
    constexpr int BP  = (BN % 32 == 16) ? BN + 24 : BN + 8; // pitch ≡ 8 mod 32

    __shared__ uint32_t As[2][128][12];
    __shared__ uint32_t Bs[2][8][BP];

    const int tid  = threadIdx.x;
    const int bm   = blockIdx.y * 128;
    const int bn   = blockIdx.x * BN;
    const int w    = tid >> 5, lane = tid & 31;
    const int wm   = w & 3,   wn   = w >> 2;
    const int g    = lane >> 2, t4 = lane & 3;
    const int cw   = Ntot - NBF;

    // ---- A prefetch lanes: 2 float4/thread ----
    int am[2], ak[2];
    const float* pa[2];
#pragma unroll
    for (int j = 0; j < 2; j++) {
        int id = tid + j * 256;
        am[j] = id >> 2;
        ak[j] = (id & 3) * 4;
        int gm = bm + am[j];
        pa[j] = (gm < M) ? A + (size_t)gm * K + ak[j] : nullptr;
    }

    // ---- B prefetch lane: one (k-pair, col4) slot per thread ----
    int bk2 = 0, bnq = 0;
    const float* pb = nullptr;
    int bpit = 0;
    const bool bv = (tid < TB2);
    if (bv) {
        bk2 = tid / NB4;
        bnq = tid % NB4;
        int gn4 = bn + bnq * 4;
        if (gn4 < NBF)       { pb = Wb + (size_t)(2 * bk2) * NBF + gn4;         bpit = NBF; }
        else if (gn4 < Ntot) { pb = Wc + (size_t)(2 * bk2) * cw  + (gn4 - NBF); bpit = cw;  }
    }

    float acc[2][NT][4];
#pragma unroll
    for (int i = 0; i < 2; i++)
#pragma unroll
        for (int j = 0; j < NT; j++)
#pragma unroll
            for (int r = 0; r < 4; r++) acc[i][j][r] = 0.0f;

    float4 ra[2], rb0, rb1;
#pragma unroll
    for (int j = 0; j < 2; j++) ra[j] = ld4(pa[j]);
    rb0 = ld4(pb);
    rb1 = ld4(pb ? pb + bpit : nullptr);

#define STORE_TILE(BUF)                                                      \
    do {                                                                     \
        _Pragma("unroll")                                                    \
        for (int j = 0; j < 2; j++) {                                        \
            uint2 hv = make_uint2(pk(ra[j].x, ra[j].y), pk(ra[j].z, ra[j].w)); \
            *reinterpret_cast<uint2*>(&As[BUF][am[j]][ak[j] >> 1]) = hv;     \
        }                                                                    \
        if (bv) {                                                            \
            uint4 bvq;                                                       \
            bvq.x = pk(rb0.x, rb1.x);                                        \
            bvq.y = pk(rb0.y, rb1.y);                                        \
            bvq.z = pk(rb0.z, rb1.z);                                        \
            bvq.w = pk(rb0.w, rb1.w);                                        \
            *reinterpret_cast<uint4*>(&Bs[BUF][bk2][bnq * 4]) = bvq;         \
        }                                                                    \
    } while (0)

    int buf = 0;
    STORE_TILE(0);
    __syncthreads();

    const int rm0 = wm * 32;
    const int cn0 = wn * NT * 8;
    const int kiter = K >> 4;

    for (int it = 1; it <= kiter; it++) {
        if (it < kiter) {
#pragma unroll
            for (int j = 0; j < 2; j++) {
                if (pa[j]) pa[j] += 16;
                ra[j] = ld4(pa[j]);
            }
            if (pb) pb += (size_t)bpit * 16;
            rb0 = ld4(pb);
            rb1 = ld4(pb ? pb + bpit : nullptr);
        }
        // compute current buffer: one k16 step
        {
            uint32_t af0[4], af1[4];
            af0[0] = As[buf][rm0 + g][t4];
            af0[1] = As[buf][rm0 + g + 8][t4];
            af0[2] = As[buf][rm0 + g][t4 + 4];
            af0[3] = As[buf][rm0 + g + 8][t4 + 4];
            af1[0] = As[buf][rm0 + 16 + g][t4];
            af1[1] = As[buf][rm0 + 16 + g + 8][t4];
            af1[2] = As[buf][rm0 + 16 + g][t4 + 4];
            af1[3] = As[buf][rm0 + 16 + g + 8][t4 + 4];
            uint32_t bf[NT][2];
#pragma unroll
            for (int j = 0; j < NT; j++) {
                int col = cn0 + j * 8 + g;
                bf[j][0] = Bs[buf][t4][col];
                bf[j][1] = Bs[buf][t4 + 4][col];
            }
#pragma unroll
            for (int j = 0; j < NT; j++) {
                mma16(acc[0][j], af0, bf[j]);
                mma16(acc[1][j], af1, bf[j]);
            }
        }
        if (it < kiter) {
            int nb = buf ^ 1;
            if (nb) STORE_TILE(1); else STORE_TILE(0);
            __syncthreads();
            buf = nb;
        }
    }
#undef STORE_TILE

    // ---- epilogue: float2 stores, bias on comb columns ----
#pragma unroll
    for (int i = 0; i < 2; i++) {
        int r0 = bm + rm0 + i * 16 + g;
#pragma unroll
        for (int j = 0; j < NT; j++) {
            int col = bn + cn0 + j * 8 + 2 * t4;
            if (col >= Ntot) continue;
            float b0 = 0.f, b1 = 0.f;
            if (col >= NBF) { b0 = bc[col - NBF]; b1 = bc[col - NBF + 1]; }
            if (r0 < M) {
                float2 v = make_float2(acc[i][j][0] + b0, acc[i][j][1] + b1);
                *reinterpret_cast<float2*>(&C[(size_t)r0 * Ntot + col]) = v;
            }
            if (r0 + 8 < M) {
                float2 v = make_float2(acc[i][j][2] + b0, acc[i][j][3] + b1);
                *reinterpret_cast<float2*>(&C[(size_t)(r0 + 8) * Ntot + col]) = v;
            }
        }
    }
}

// ---------------- fused aggregation + combine + bias (+relu / +log_softmax) --
template<int NBF, int F, bool RELU, bool LSM>
__global__ __launch_bounds__(256)
void k_agg(const float* __restrict__ lin, int stride,
           const float* __restrict__ bias,
           float* __restrict__ out, int n)
{
    constexpr int HF  = 8 * F;
    constexpr int NI  = HF / 32;
    constexpr int C4  = (NBF + 127) / 128;
    constexpr int NF4 = NBF / 4;
    __shared__ float agg_s[8][3 * NBF];
    __shared__ float comb_s[8][96];

    int gw   = (blockIdx.x * 256 + threadIdx.x) >> 5;
    int lane = threadIdx.x & 31;
    int lw   = threadIdx.x >> 5;
    if (gw >= n) return;

    int s = g_off[gw], e = g_off[gw + 1];
    int deg = e - s;

    float4 vsym[C4], vsum[C4], vmax[C4];
#pragma unroll
    for (int q = 0; q < C4; q++) {
        vsym[q] = make_float4(0.f, 0.f, 0.f, 0.f);
        vsum[q] = make_float4(0.f, 0.f, 0.f, 0.f);
        vmax[q] = make_float4(-INFINITY, -INFINITY, -INFINITY, -INFINITY);
    }

    int t = s;
    for (; t + 4 <= e; t += 4) {
        int c0 = g_adj[t], c1 = g_adj[t + 1], c2 = g_adj[t + 2], c3 = g_adj[t + 3];
        float d0 = g_dinv[c0], d1 = g_dinv[c1], d2 = g_dinv[c2], d3 = g_dinv[c3];
        const float4* s0 = reinterpret_cast<const float4*>(lin + (size_t)c0 * stride);
        const float4* s1 = reinterpret_cast<const float4*>(lin + (size_t)c1 * stride);
        const float4* s2 = reinterpret_cast<const float4*>(lin + (size_t)c2 * stride);
        const float4* s3 = reinterpret_cast<const float4*>(lin + (size_t)c3 * stride);
#pragma unroll
        for (int q = 0; q < C4; q++) {
            int i4 = lane + q * 32;
            if (C4 > 1 && i4 >= NF4) break;
            float4 v0 = s0[i4], v1 = s1[i4], v2 = s2[i4], v3 = s3[i4];
            vsym[q].x += (d0 * v0.x + d1 * v1.x) + (d2 * v2.x + d3 * v3.x);
            vsym[q].y += (d0 * v0.y + d1 * v1.y) + (d2 * v2.y + d3 * v3.y);
            vsym[q].z += (d0 * v0.z + d1 * v1.z) + (d2 * v2.z + d3 * v3.z);
            vsym[q].w += (d0 * v0.w + d1 * v1.w) + (d2 * v2.w + d3 * v3.w);
            vsum[q].x += (v0.x + v1.x) + (v2.x + v3.x);
            vsum[q].y += (v0.y + v1.y) + (v2.y + v3.y);
            vsum[q].z += (v0.z + v1.z) + (v2.z + v3.z);
            vsum[q].w += (v0.w + v1.w) + (v2.w + v3.w);
            vmax[q].x = fmaxf(vmax[q].x, fmaxf(fmaxf(v0.x, v1.x), fmaxf(v2.x, v3.x)));
            vmax[q].y = fmaxf(vmax[q].y, fmaxf(fmaxf(v0.y, v1.y), fmaxf(v2.y, v3.y)));
            vmax[q].z = fmaxf(vmax[q].z, fmaxf(fmaxf(v0.z, v1.z), fmaxf(v2.z, v3.z)));
            vmax[q].w = fmaxf(vmax[q].w, fmaxf(fmaxf(v0.w, v1.w), fmaxf(v2.w, v3.w)));
        }
    }
    for (; t < e; t++) {
        int c0 = g_adj[t];
        float d0 = g_dinv[c0];
        const float4* s0 = reinterpret_cast<const float4*>(lin + (size_t)c0 * stride);
#pragma unroll
        for (int q = 0; q < C4; q++) {
            int i4 = lane + q * 32;
            if (C4 > 1 && i4 >= NF4) break;
            float4 v0 = s0[i4];
            vsym[q].x += d0 * v0.x; vsym[q].y += d0 * v0.y;
            vsym[q].z += d0 * v0.z; vsym[q].w += d0 * v0.w;
            vsum[q].x += v0.x; vsum[q].y += v0.y;
            vsum[q].z += v0.z; vsum[q].w += v0.w;
            vmax[q].x = fmaxf(vmax[q].x, v0.x); vmax[q].y = fmaxf(vmax[q].y, v0.y);
            vmax[q].z = fmaxf(vmax[q].z, v0.z); vmax[q].w = fmaxf(vmax[q].w, v0.w);
        }
    }

    float dn   = g_dinv[gw];
    float invd = (deg > 0) ? (1.0f / (float)deg) : 0.0f;

    float4* arow0 = reinterpret_cast<float4*>(&agg_s[lw][0]);
    float4* arow1 = reinterpret_cast<float4*>(&agg_s[lw][NBF]);
    float4* arow2 = reinterpret_cast<float4*>(&agg_s[lw][2 * NBF]);
#pragma unroll
    for (int q = 0; q < C4; q++) {
        int i4 = lane + q * 32;
        if (C4 > 1 && i4 >= NF4) break;
        float4 sy = vsym[q];
        sy.x *= dn; sy.y *= dn; sy.z *= dn; sy.w *= dn;
        float4 me = vsum[q];
        me.x *= invd; me.y *= invd; me.z *= invd; me.w *= invd;
        float4 mx = vmax[q];
        if (deg == 0) mx = make_float4(0.f, 0.f, 0.f, 0.f);
        arow0[i4] = sy;
        arow1[i4] = me;
        arow2[i4] = mx;
    }

    const float* comb = lin + (size_t)gw * stride + NBF;
    comb_s[lw][lane]      = comb[lane];
    comb_s[lw][lane + 32] = comb[lane + 32];
    comb_s[lw][lane + 64] = comb[lane + 64];
    __syncwarp();

    float vals[NI];
#pragma unroll
    for (int i = 0; i < NI; i++) {
        int c = lane + i * 32;
        int h = c / F, f = c % F;
        float v = bias[c];
        const float* cb = &comb_s[lw][h * 12];
        const float* ag = &agg_s[lw][0];
#pragma unroll
        for (int k = 0; k < 12; k++) v = fmaf(cb[k], ag[k * F + f], v);
        if (RELU) v = fmaxf(v, 0.0f);
        vals[i] = v;
    }

    if (!LSM) {
#pragma unroll
        for (int i = 0; i < NI; i++)
            out[(size_t)gw * HF + lane + i * 32] = vals[i];
    } else {
        float m = -INFINITY;
#pragma unroll
        for (int i = 0; i < NI; i++) {
            int c = lane + i * 32;
            m = fmaxf(m, (c < OUTT) ? vals[i] : -INFINITY);
        }
#pragma unroll
        for (int o = 16; o; o >>= 1) m = fmaxf(m, __shfl_xor_sync(0xffffffffu, m, o));
        float sum = 0.0f;
#pragma unroll
        for (int i = 0; i < NI; i++) {
            int c = lane + i * 32;
            if (c < OUTT) sum += expf(vals[i] - m);
        }
#pragma unroll
        for (int o = 16; o; o >>= 1) sum += __shfl_xor_sync(0xffffffffu, sum, o);
        float l = m + logf(sum);
#pragma unroll
        for (int i = 0; i < NI; i++) {
            int c = lane + i * 32;
            if (c < OUTT) out[(size_t)gw * OUTT + c] = vals[i] - l;
        }
    }
}

// ---------------- launch --------------------------------------------------------
extern "C" void kernel_launch(void* const* d_in, const int* in_sizes, int n_in,
                              void* d_out, int out_size)
{
    const float* x   = (const float*)d_in[0];
    const int*   ei  = (const int*)d_in[1];
    int N = in_sizes[0] / 128;
    int E = in_sizes[1] / 2;
    if (N > NMAX) N = NMAX;
    if (E > EMAX) E = EMAX;
    const int* row = ei;
    const int* col = ei + E;

    const float* Wb0 = (const float*)d_in[2];
    const float* Wc0 = (const float*)d_in[3];
    const float* bc0 = (const float*)d_in[4];
    const float* b0  = (const float*)d_in[5];
    const float* Wb1 = (const float*)d_in[6];
    const float* Wc1 = (const float*)d_in[7];
    const float* bc1 = (const float*)d_in[8];
    const float* b1  = (const float*)d_in[9];
    const float* Wb2 = (const float*)d_in[10];
    const float* Wc2 = (const float*)d_in[11];
    const float* bc2 = (const float*)d_in[12];
    const float* b2  = (const float*)d_in[13];

    float* lin; float* hA; float* hB;
    cudaGetSymbolAddress((void**)&lin, g_lin);
    cudaGetSymbolAddress((void**)&hA,  g_hA);
    cudaGetSymbolAddress((void**)&hB,  g_hB);

    const int T  = 256;
    const int gy = (N + 127) / 128;
    const int ab = (N + 7) / 8;
    const int sb = (N + 255) / 256;

    // CSR build interleaved with layer-0 GEMM (independent of CSR)
    k_zero   <<<(N + T - 1) / T, T>>>(N);
    k_deg    <<<(E + T - 1) / T, T>>>(row, E);
    k_dinv   <<<(N + T - 1) / T, T>>>(N);
    k_gemm_h<7><<<dim3(2, gy), 256>>>(x, Wb0, Wc0, bc0, lin, N, 128, 128, 224);
    k_scan1  <<<sb, 256>>>(N);
    k_scan2  <<<1, 256>>>(sb);
    k_scan3  <<<sb, 256>>>(N, E);
    k_scatter<<<(E + T - 1) / T, T>>>(row, col, E);

    k_agg<128, 32, true, false><<<ab, 256>>>(lin, 224, b0, hA, N);

    k_gemm_h<7><<<dim3(2, gy), 256>>>(hA, Wb1, Wc1, bc1, lin, N, 256, 128, 224);
    k_agg<128, 32, true, false><<<ab, 256>>>(lin, 224, b1, hB, N);

    k_gemm_h<6><<<dim3(3, gy), 256>>>(hB, Wb2, Wc2, bc2, lin, N, 256, 176, 272);
    // layer-2 aggregation fused with log_softmax, writes d_out directly
    k_agg<176, 44, false, true><<<ab, 256>>>(lin, 272, b2, (float*)d_out, N);
}

// round 6
// speedup vs baseline: 1.2384x; 1.0445x over previous
#include <cuda_runtime.h>
#include <cuda_fp16.h>
#include <math.h>
#include <stdint.h>

#define NMAX   50000
#define EMAX   600000
#define OUTT   349
#define MAXNTOT 272

// ---------------- scratch (device globals) ----------------------------------
__device__ int    g_deg[NMAX];
__device__ float  g_dinv[NMAX];
__device__ int    g_off[NMAX + 1];
__device__ int    g_cur[NMAX];
__device__ int    g_adj[EMAX];
__device__ int    g_bsum[256];
__device__ float  g_lin[(size_t)NMAX * MAXNTOT];
__device__ __half g_xh[(size_t)NMAX * 128];
__device__ __half g_hA[(size_t)NMAX * 256];
__device__ __half g_hB[(size_t)NMAX * 256];
__device__ __half g_wt0[224 * 128];
__device__ __half g_wt1[224 * 256];
__device__ __half g_wt2[288 * 256];

// ---------------- converts ----------------------------------------------------
__global__ void k_cvt_x(const float* __restrict__ x, __half2* __restrict__ xh, int n4) {
    int i = blockIdx.x * blockDim.x + threadIdx.x;
    if (i < n4) {
        float4 v = reinterpret_cast<const float4*>(x)[i];
        xh[2 * i]     = __floats2half2_rn(v.x, v.y);
        xh[2 * i + 1] = __floats2half2_rn(v.z, v.w);
    }
}

// Wt[n][k] = n<NBF ? Wb[k][n] : (n<Ntot ? Wc[k][n-NBF] : 0)
__global__ void k_cvt_w(const float* __restrict__ Wb, const float* __restrict__ Wc,
                        __half* __restrict__ Wt, int K, int NBF, int Ntot, int NtotPad) {
    int idx = blockIdx.x * blockDim.x + threadIdx.x;
    if (idx >= NtotPad * K) return;
    int n = idx / K, k = idx % K;
    float v = 0.0f;
    if (n < NBF)       v = Wb[k * NBF + n];
    else if (n < Ntot) v = Wc[k * (Ntot - NBF) + (n - NBF)];
    Wt[idx] = __float2half_rn(v);
}

// ---------------- CSR build --------------------------------------------------
__global__ void k_zero(int n) {
    int i = blockIdx.x * blockDim.x + threadIdx.x;
    if (i < n) g_deg[i] = 0;
}

__global__ void k_deg(const int* __restrict__ row, int e) {
    int i = blockIdx.x * blockDim.x + threadIdx.x;
    if (i < e) atomicAdd(&g_deg[row[i]], 1);
}

__global__ void k_dinv(int n) {
    int i = blockIdx.x * blockDim.x + threadIdx.x;
    if (i < n) {
        int d = g_deg[i];
        g_dinv[i] = (d > 0) ? rsqrtf((float)d) : 0.0f;
    }
}

__global__ void k_scan1(int n) {
    __shared__ int sh[256];
    int t = threadIdx.x;
    int i = blockIdx.x * 256 + t;
    sh[t] = (i < n) ? g_deg[i] : 0;
    __syncthreads();
#pragma unroll
    for (int s = 128; s; s >>= 1) {
        if (t < s) sh[t] += sh[t + s];
        __syncthreads();
    }
    if (t == 0) g_bsum[blockIdx.x] = sh[0];
}

__global__ void k_scan2(int nb) {
    __shared__ int sh[256];
    int t = threadIdx.x;
    int v = (t < nb) ? g_bsum[t] : 0;
    sh[t] = v;
    __syncthreads();
#pragma unroll
    for (int d = 1; d < 256; d <<= 1) {
        int u = (t >= d) ? sh[t - d] : 0;
        __syncthreads();
        sh[t] += u;
        __syncthreads();
    }
    if (t < nb) g_bsum[t] = sh[t] - v;
}

__global__ void k_scan3(int n, int total) {
    __shared__ int sh[256];
    int t = threadIdx.x;
    int i = blockIdx.x * 256 + t;
    int v = (i < n) ? g_deg[i] : 0;
    sh[t] = v;
    __syncthreads();
#pragma unroll
    for (int d = 1; d < 256; d <<= 1) {
        int u = (t >= d) ? sh[t - d] : 0;
        __syncthreads();
        sh[t] += u;
        __syncthreads();
    }
    int excl = sh[t] - v + g_bsum[blockIdx.x];
    if (i < n) { g_off[i] = excl; g_cur[i] = excl; }
    if (blockIdx.x == 0 && t == 0) g_off[n] = total;
}

__global__ void k_scatter(const int* __restrict__ row, const int* __restrict__ col, int e) {
    int i = blockIdx.x * blockDim.x + threadIdx.x;
    if (i < e) {
        int r = row[i];
        int p = atomicAdd(&g_cur[r], 1);
        g_adj[p] = col[i];
    }
}

// ---------------- fp16 tensor-core GEMM, cp.async 4-stage pipeline ------------
__device__ __forceinline__ void mma16(float* c, const uint32_t* a, const uint32_t* b) {
    asm volatile(
        "mma.sync.aligned.m16n8k16.row.col.f32.f16.f16.f32 "
        "{%0,%1,%2,%3}, {%4,%5,%6,%7}, {%8,%9}, {%0,%1,%2,%3};"
        : "+f"(c[0]), "+f"(c[1]), "+f"(c[2]), "+f"(c[3])
        : "r"(a[0]), "r"(a[1]), "r"(a[2]), "r"(a[3]), "r"(b[0]), "r"(b[1]));
}

__device__ __forceinline__ void cpa16(uint32_t saddr, const void* gptr, bool pred) {
    int sz = pred ? 16 : 0;
    asm volatile("cp.async.ca.shared.global [%0], [%1], 16, %2;"
                 :: "r"(saddr), "l"(gptr), "r"(sz));
}

// A: [M,K] fp16 K-major.  Wt: [NtotPad,K] fp16 K-major (pre-fused, padded).
// As/Bs rows: 16 halves (8 uint32) at pitch 12 uint32 (conflict-free frags).
template<int NT>
__global__ __launch_bounds__(256)
void k_gemm_h(const __half* __restrict__ A, const __half* __restrict__ Wt,
              const float* __restrict__ bc,
              float* __restrict__ C, int M, int K, int NBF, int Ntot)
{
    constexpr int BN = 16 * NT;
    __shared__ __align__(16) uint32_t As[4][128][12];
    __shared__ __align__(16) uint32_t Bs[4][BN][12];

    const int tid  = threadIdx.x;
    const int bm   = blockIdx.y * 128;
    const int bn   = blockIdx.x * BN;
    const int w    = tid >> 5, lane = tid & 31;
    const int wm   = w & 3,   wn   = w >> 2;
    const int g    = lane >> 2, t4 = lane & 3;

    // copy lanes: row = tid>>1, half = tid&1 (16B chunk)
    const int crow = tid >> 1, ch = tid & 1;
    const bool aval = (bm + crow) < M;
    const __half* agp = A  + (size_t)(bm + crow) * K + ch * 8;
    const __half* bgp = Wt + (size_t)(bn + crow) * K + ch * 8;
    const bool bv = (tid < 2 * BN);

    uint32_t a_s = (uint32_t)__cvta_generic_to_shared(&As[0][crow][ch * 4]);
    uint32_t b_s = (uint32_t)__cvta_generic_to_shared(&Bs[0][crow][ch * 4]);
    constexpr uint32_t ASTRIDE = 128 * 12 * 4;
    constexpr uint32_t BSTRIDE = BN * 12 * 4;

#define ISSUE(S, K0)                                                   \
    do {                                                               \
        cpa16(a_s + (S) * ASTRIDE, agp + (K0), aval);                  \
        if (bv) cpa16(b_s + (S) * BSTRIDE, bgp + (K0), true);          \
        asm volatile("cp.async.commit_group;");                        \
    } while (0)

    float acc[2][NT][4];
#pragma unroll
    for (int i = 0; i < 2; i++)
#pragma unroll
        for (int j = 0; j < NT; j++)
#pragma unroll
            for (int r = 0; r < 4; r++) acc[i][j][r] = 0.0f;

    const int kiter = K >> 4;  // >= 8 always
    ISSUE(0, 0);
    ISSUE(1, 16);
    ISSUE(2, 32);

    const int rm0 = wm * 32;
    const int cn0 = wn * NT * 8;

    for (int it = 0; it < kiter; it++) {
        asm volatile("cp.async.wait_group 2;");
        __syncthreads();
        const int buf = it & 3;
        {
            uint32_t af0[4], af1[4];
            af0[0] = As[buf][rm0 + g][t4];
            af0[1] = As[buf][rm0 + g + 8][t4];
            af0[2] = As[buf][rm0 + g][t4 + 4];
            af0[3] = As[buf][rm0 + g + 8][t4 + 4];
            af1[0] = As[buf][rm0 + 16 + g][t4];
            af1[1] = As[buf][rm0 + 16 + g + 8][t4];
            af1[2] = As[buf][rm0 + 16 + g][t4 + 4];
            af1[3] = As[buf][rm0 + 16 + g + 8][t4 + 4];
            uint32_t bf[NT][2];
#pragma unroll
            for (int j = 0; j < NT; j++) {
                int col = cn0 + j * 8 + g;
                bf[j][0] = Bs[buf][col][t4];
                bf[j][1] = Bs[buf][col][t4 + 4];
            }
#pragma unroll
            for (int j = 0; j < NT; j++) {
                mma16(acc[0][j], af0, bf[j]);
                mma16(acc[1][j], af1, bf[j]);
            }
        }
        __syncthreads();
        if (it + 3 < kiter) ISSUE((it + 3) & 3, (it + 3) * 16);
        else asm volatile("cp.async.commit_group;");
    }
#undef ISSUE

    // ---- epilogue: float2 stores, bias on comb columns ----
#pragma unroll
    for (int i = 0; i < 2; i++) {
        int r0 = bm + rm0 + i * 16 + g;
#pragma unroll
        for (int j = 0; j < NT; j++) {
            int col = bn + cn0 + j * 8 + 2 * t4;
            if (col >= Ntot) continue;
            float b0 = 0.f, b1 = 0.f;
            if (col >= NBF) { b0 = bc[col - NBF]; b1 = bc[col - NBF + 1]; }
            if (r0 < M) {
                float2 v = make_float2(acc[i][j][0] + b0, acc[i][j][1] + b1);
                *reinterpret_cast<float2*>(&C[(size_t)r0 * Ntot + col]) = v;
            }
            if (r0 + 8 < M) {
                float2 v = make_float2(acc[i][j][2] + b0, acc[i][j][3] + b1);
                *reinterpret_cast<float2*>(&C[(size_t)(r0 + 8) * Ntot + col]) = v;
            }
        }
    }
}

// ---------------- fused aggregation + combine + bias (+relu / +log_softmax) --
// LSM=false: out is __half* [N, 8F].  LSM=true: out is float* [N, OUTT].
template<int NBF, int F, bool RELU, bool LSM>
__global__ __launch_bounds__(256)
void k_agg(const float* __restrict__ lin, int stride,
           const float* __restrict__ bias,
           void* __restrict__ out_v, int n)
{
    constexpr int HF  = 8 * F;
    constexpr int NI  = HF / 32;
    constexpr int C4  = (NBF + 127) / 128;
    constexpr int NF4 = NBF / 4;
    __shared__ float agg_s[8][3 * NBF];
    __shared__ float comb_s[8][96];

    int gw   = (blockIdx.x * 256 + threadIdx.x) >> 5;
    int lane = threadIdx.x & 31;
    int lw   = threadIdx.x >> 5;
    if (gw >= n) return;

    int s = g_off[gw], e = g_off[gw + 1];
    int deg = e - s;

    float4 vsym[C4], vsum[C4], vmax[C4];
#pragma unroll
    for (int q = 0; q < C4; q++) {
        vsym[q] = make_float4(0.f, 0.f, 0.f, 0.f);
        vsum[q] = make_float4(0.f, 0.f, 0.f, 0.f);
        vmax[q] = make_float4(-INFINITY, -INFINITY, -INFINITY, -INFINITY);
    }

    int t = s;
    for (; t + 4 <= e; t += 4) {
        int c0 = g_adj[t], c1 = g_adj[t + 1], c2 = g_adj[t + 2], c3 = g_adj[t + 3];
        float d0 = g_dinv[c0], d1 = g_dinv[c1], d2 = g_dinv[c2], d3 = g_dinv[c3];
        const float4* s0 = reinterpret_cast<const float4*>(lin + (size_t)c0 * stride);
        const float4* s1 = reinterpret_cast<const float4*>(lin + (size_t)c1 * stride);
        const float4* s2 = reinterpret_cast<const float4*>(lin + (size_t)c2 * stride);
        const float4* s3 = reinterpret_cast<const float4*>(lin + (size_t)c3 * stride);
#pragma unroll
        for (int q = 0; q < C4; q++) {
            int i4 = lane + q * 32;
            if (C4 > 1 && i4 >= NF4) break;
            float4 v0 = s0[i4], v1 = s1[i4], v2 = s2[i4], v3 = s3[i4];
            vsym[q].x += (d0 * v0.x + d1 * v1.x) + (d2 * v2.x + d3 * v3.x);
            vsym[q].y += (d0 * v0.y + d1 * v1.y) + (d2 * v2.y + d3 * v3.y);
            vsym[q].z += (d0 * v0.z + d1 * v1.z) + (d2 * v2.z + d3 * v3.z);
            vsym[q].w += (d0 * v0.w + d1 * v1.w) + (d2 * v2.w + d3 * v3.w);
            vsum[q].x += (v0.x + v1.x) + (v2.x + v3.x);
            vsum[q].y += (v0.y + v1.y) + (v2.y + v3.y);
            vsum[q].z += (v0.z + v1.z) + (v2.z + v3.z);
            vsum[q].w += (v0.w + v1.w) + (v2.w + v3.w);
            vmax[q].x = fmaxf(vmax[q].x, fmaxf(fmaxf(v0.x, v1.x), fmaxf(v2.x, v3.x)));
            vmax[q].y = fmaxf(vmax[q].y, fmaxf(fmaxf(v0.y, v1.y), fmaxf(v2.y, v3.y)));
            vmax[q].z = fmaxf(vmax[q].z, fmaxf(fmaxf(v0.z, v1.z), fmaxf(v2.z, v3.z)));
            vmax[q].w = fmaxf(vmax[q].w, fmaxf(fmaxf(v0.w, v1.w), fmaxf(v2.w, v3.w)));
        }
    }
    for (; t < e; t++) {
        int c0 = g_adj[t];
        float d0 = g_dinv[c0];
        const float4* s0 = reinterpret_cast<const float4*>(lin + (size_t)c0 * stride);
#pragma unroll
        for (int q = 0; q < C4; q++) {
            int i4 = lane + q * 32;
            if (C4 > 1 && i4 >= NF4) break;
            float4 v0 = s0[i4];
            vsym[q].x += d0 * v0.x; vsym[q].y += d0 * v0.y;
            vsym[q].z += d0 * v0.z; vsym[q].w += d0 * v0.w;
            vsum[q].x += v0.x; vsum[q].y += v0.y;
            vsum[q].z += v0.z; vsum[q].w += v0.w;
            vmax[q].x = fmaxf(vmax[q].x, v0.x); vmax[q].y = fmaxf(vmax[q].y, v0.y);
            vmax[q].z = fmaxf(vmax[q].z, v0.z); vmax[q].w = fmaxf(vmax[q].w, v0.w);
        }
    }

    float dn   = g_dinv[gw];
    float invd = (deg > 0) ? (1.0f / (float)deg) : 0.0f;

    float4* arow0 = reinterpret_cast<float4*>(&agg_s[lw][0]);
    float4* arow1 = reinterpret_cast<float4*>(&agg_s[lw][NBF]);
    float4* arow2 = reinterpret_cast<float4*>(&agg_s[lw][2 * NBF]);
#pragma unroll
    for (int q = 0; q < C4; q++) {
        int i4 = lane + q * 32;
        if (C4 > 1 && i4 >= NF4) break;
        float4 sy = vsym[q];
        sy.x *= dn; sy.y *= dn; sy.z *= dn; sy.w *= dn;
        float4 me = vsum[q];
        me.x *= invd; me.y *= invd; me.z *= invd; me.w *= invd;
        float4 mx = vmax[q];
        if (deg == 0) mx = make_float4(0.f, 0.f, 0.f, 0.f);
        arow0[i4] = sy;
        arow1[i4] = me;
        arow2[i4] = mx;
    }

    const float* comb = lin + (size_t)gw * stride + NBF;
    comb_s[lw][lane]      = comb[lane];
    comb_s[lw][lane + 32] = comb[lane + 32];
    comb_s[lw][lane + 64] = comb[lane + 64];
    __syncwarp();

    float vals[NI];
#pragma unroll
    for (int i = 0; i < NI; i++) {
        int c = lane + i * 32;
        int h = c / F, f = c % F;
        float v = bias[c];
        const float* cb = &comb_s[lw][h * 12];
        const float* ag = &agg_s[lw][0];
#pragma unroll
        for (int k = 0; k < 12; k++) v = fmaf(cb[k], ag[k * F + f], v);
        if (RELU) v = fmaxf(v, 0.0f);
        vals[i] = v;
    }

    if (!LSM) {
        __half* out = (__half*)out_v;
#pragma unroll
        for (int i = 0; i < NI; i++)
            out[(size_t)gw * HF + lane + i * 32] = __float2half_rn(vals[i]);
    } else {
        float* out = (float*)out_v;
        float m = -INFINITY;
#pragma unroll
        for (int i = 0; i < NI; i++) {
            int c = lane + i * 32;
            m = fmaxf(m, (c < OUTT) ? vals[i] : -INFINITY);
        }
#pragma unroll
        for (int o = 16; o; o >>= 1) m = fmaxf(m, __shfl_xor_sync(0xffffffffu, m, o));
        float sum = 0.0f;
#pragma unroll
        for (int i = 0; i < NI; i++) {
            int c = lane + i * 32;
            if (c < OUTT) sum += expf(vals[i] - m);
        }
#pragma unroll
        for (int o = 16; o; o >>= 1) sum += __shfl_xor_sync(0xffffffffu, sum, o);
        float l = m + logf(sum);
#pragma unroll
        for (int i = 0; i < NI; i++) {
            int c = lane + i * 32;
            if (c < OUTT) out[(size_t)gw * OUTT + c] = vals[i] - l;
        }
    }
}

// ---------------- launch --------------------------------------------------------
extern "C" void kernel_launch(void* const* d_in, const int* in_sizes, int n_in,
                              void* d_out, int out_size)
{
    const float* x   = (const float*)d_in[0];
    const int*   ei  = (const int*)d_in[1];
    int N = in_sizes[0] / 128;
    int E = in_sizes[1] / 2;
    if (N > NMAX) N = NMAX;
    if (E > EMAX) E = EMAX;
    const int* row = ei;
    const int* col = ei + E;

    const float* Wb0 = (const float*)d_in[2];
    const float* Wc0 = (const float*)d_in[3];
    const float* bc0 = (const float*)d_in[4];
    const float* b0  = (const float*)d_in[5];
    const float* Wb1 = (const float*)d_in[6];
    const float* Wc1 = (const float*)d_in[7];
    const float* bc1 = (const float*)d_in[8];
    const float* b1  = (const float*)d_in[9];
    const float* Wb2 = (const float*)d_in[10];
    const float* Wc2 = (const float*)d_in[11];
    const float* bc2 = (const float*)d_in[12];
    const float* b2  = (const float*)d_in[13];

    float* lin; __half* xh; __half* hA; __half* hB;
    __half* wt0; __half* wt1; __half* wt2;
    cudaGetSymbolAddress((void**)&lin, g_lin);
    cudaGetSymbolAddress((void**)&xh,  g_xh);
    cudaGetSymbolAddress((void**)&hA,  g_hA);
    cudaGetSymbolAddress((void**)&hB,  g_hB);
    cudaGetSymbolAddress((void**)&wt0, g_wt0);
    cudaGetSymbolAddress((void**)&wt1, g_wt1);
    cudaGetSymbolAddress((void**)&wt2, g_wt2);

    const int T  = 256;
    const int gy = (N + 127) / 128;
    const int ab = (N + 7) / 8;
    const int sb = (N + 255) / 256;
    const int n4 = N * 128 / 4;

    // converts + CSR build (all independent of each other except scans)
    k_cvt_x<<<(n4 + T - 1) / T, T>>>(x, (__half2*)xh, n4);
    k_cvt_w<<<(224 * 128 + T - 1) / T, T>>>(Wb0, Wc0, wt0, 128, 128, 224, 224);
    k_cvt_w<<<(224 * 256 + T - 1) / T, T>>>(Wb1, Wc1, wt1, 256, 128, 224, 224);
    k_cvt_w<<<(288 * 256 + T - 1) / T, T>>>(Wb2, Wc2, wt2, 256, 176, 272, 288);
    k_zero   <<<(N + T - 1) / T, T>>>(N);
    k_deg    <<<(E + T - 1) / T, T>>>(row, E);
    k_dinv   <<<(N + T - 1) / T, T>>>(N);
    k_gemm_h<7><<<dim3(2, gy), 256>>>(xh, wt0, bc0, lin, N, 128, 128, 224);
    k_scan1  <<<sb, 256>>>(N);
    k_scan2  <<<1, 256>>>(sb);
    k_scan3  <<<sb, 256>>>(N, E);
    k_scatter<<<(E + T - 1) / T, T>>>(row, col, E);

    k_agg<128, 32, true, false><<<ab, 256>>>(lin, 224, b0, hA, N);

    k_gemm_h<7><<<dim3(2, gy), 256>>>(hA, wt1, bc1, lin, N, 256, 128, 224);
    k_agg<128, 32, true, false><<<ab, 256>>>(lin, 224, b1, hB, N);

    k_gemm_h<6><<<dim3(3, gy), 256>>>(hB, wt2, bc2, lin, N, 256, 176, 272);
    k_agg<176, 44, false, true><<<ab, 256>>>(lin, 272, b2, d_out, N);
}

// round 7
// speedup vs baseline: 1.3099x; 1.0577x over previous
#include <cuda_runtime.h>
#include <cuda_fp16.h>
#include <math.h>
#include <stdint.h>

#define NMAX   50000
#define EMAX   600000
#define OUTT   349

// ---------------- scratch (device globals) ----------------------------------
__device__ int    g_deg[NMAX];
__device__ float  g_dinv[NMAX];
__device__ int    g_off[NMAX + 1];
__device__ int    g_cur[NMAX];
__device__ int    g_adj[EMAX];
__device__ int    g_bsum[256];
__device__ __half g_linh[(size_t)NMAX * 176];   // bases (fp16), pitch = NBF
__device__ float  g_linc[(size_t)NMAX * 96];    // comb (fp32), pitch = 96
__device__ __half g_xh[(size_t)NMAX * 128];
__device__ __half g_hA[(size_t)NMAX * 256];
__device__ __half g_hB[(size_t)NMAX * 256];
__device__ __half g_wt0[224 * 128];
__device__ __half g_wt1[224 * 256];
__device__ __half g_wt2[288 * 256];

// ---------------- converts ----------------------------------------------------
__global__ void k_cvt_x(const float* __restrict__ x, __half2* __restrict__ xh, int n4) {
    int i = blockIdx.x * blockDim.x + threadIdx.x;
    if (i < n4) {
        float4 v = reinterpret_cast<const float4*>(x)[i];
        xh[2 * i]     = __floats2half2_rn(v.x, v.y);
        xh[2 * i + 1] = __floats2half2_rn(v.z, v.w);
    }
}

__global__ void k_cvt_w(const float* __restrict__ Wb, const float* __restrict__ Wc,
                        __half* __restrict__ Wt, int K, int NBF, int Ntot, int NtotPad) {
    int idx = blockIdx.x * blockDim.x + threadIdx.x;
    if (idx >= NtotPad * K) return;
    int n = idx / K, k = idx % K;
    float v = 0.0f;
    if (n < NBF)       v = Wb[k * NBF + n];
    else if (n < Ntot) v = Wc[k * (Ntot - NBF) + (n - NBF)];
    Wt[idx] = __float2half_rn(v);
}

// ---------------- CSR build --------------------------------------------------
__global__ void k_zero(int n) {
    int i = blockIdx.x * blockDim.x + threadIdx.x;
    if (i < n) g_deg[i] = 0;
}

__global__ void k_deg(const int* __restrict__ row, int e) {
    int i = blockIdx.x * blockDim.x + threadIdx.x;
    if (i < e) atomicAdd(&g_deg[row[i]], 1);
}

__global__ void k_dinv(int n) {
    int i = blockIdx.x * blockDim.x + threadIdx.x;
    if (i < n) {
        int d = g_deg[i];
        g_dinv[i] = (d > 0) ? rsqrtf((float)d) : 0.0f;
    }
}

__global__ void k_scan1(int n) {
    __shared__ int sh[256];
    int t = threadIdx.x;
    int i = blockIdx.x * 256 + t;
    sh[t] = (i < n) ? g_deg[i] : 0;
    __syncthreads();
#pragma unroll
    for (int s = 128; s; s >>= 1) {
        if (t < s) sh[t] += sh[t + s];
        __syncthreads();
    }
    if (t == 0) g_bsum[blockIdx.x] = sh[0];
}

__global__ void k_scan2(int nb) {
    __shared__ int sh[256];
    int t = threadIdx.x;
    int v = (t < nb) ? g_bsum[t] : 0;
    sh[t] = v;
    __syncthreads();
#pragma unroll
    for (int d = 1; d < 256; d <<= 1) {
        int u = (t >= d) ? sh[t - d] : 0;
        __syncthreads();
        sh[t] += u;
        __syncthreads();
    }
    if (t < nb) g_bsum[t] = sh[t] - v;
}

__global__ void k_scan3(int n, int total) {
    __shared__ int sh[256];
    int t = threadIdx.x;
    int i = blockIdx.x * 256 + t;
    int v = (i < n) ? g_deg[i] : 0;
    sh[t] = v;
    __syncthreads();
#pragma unroll
    for (int d = 1; d < 256; d <<= 1) {
        int u = (t >= d) ? sh[t - d] : 0;
        __syncthreads();
        sh[t] += u;
        __syncthreads();
    }
    int excl = sh[t] - v + g_bsum[blockIdx.x];
    if (i < n) { g_off[i] = excl; g_cur[i] = excl; }
    if (blockIdx.x == 0 && t == 0) g_off[n] = total;
}

__global__ void k_scatter(const int* __restrict__ row, const int* __restrict__ col, int e) {
    int i = blockIdx.x * blockDim.x + threadIdx.x;
    if (i < e) {
        int r = row[i];
        int p = atomicAdd(&g_cur[r], 1);
        g_adj[p] = col[i];
    }
}

// ---------------- fp16 tensor-core GEMM, cp.async 4-stage pipeline ------------
__device__ __forceinline__ void mma16(float* c, const uint32_t* a, const uint32_t* b) {
    asm volatile(
        "mma.sync.aligned.m16n8k16.row.col.f32.f16.f16.f32 "
        "{%0,%1,%2,%3}, {%4,%5,%6,%7}, {%8,%9}, {%0,%1,%2,%3};"
        : "+f"(c[0]), "+f"(c[1]), "+f"(c[2]), "+f"(c[3])
        : "r"(a[0]), "r"(a[1]), "r"(a[2]), "r"(a[3]), "r"(b[0]), "r"(b[1]));
}

__device__ __forceinline__ void cpa16(uint32_t saddr, const void* gptr, bool pred) {
    int sz = pred ? 16 : 0;
    asm volatile("cp.async.ca.shared.global [%0], [%1], 16, %2;"
                 :: "r"(saddr), "l"(gptr), "r"(sz));
}

// A: [M,K] fp16 K-major.  Wt: [NtotPad,K] fp16 K-major (pre-fused, padded).
// Output split: base cols -> Ch fp16 (pitch NBF), comb cols -> Cc fp32 (pitch 96) + bc.
template<int NT>
__global__ __launch_bounds__(256)
void k_gemm_h(const __half* __restrict__ A, const __half* __restrict__ Wt,
              const float* __restrict__ bc,
              __half* __restrict__ Ch, float* __restrict__ Cc,
              int M, int K, int NBF, int Ntot)
{
    constexpr int BN = 16 * NT;
    __shared__ __align__(16) uint32_t As[4][128][12];
    __shared__ __align__(16) uint32_t Bs[4][BN][12];

    const int tid  = threadIdx.x;
    const int bm   = blockIdx.y * 128;
    const int bn   = blockIdx.x * BN;
    const int w    = tid >> 5, lane = tid & 31;
    const int wm   = w & 3,   wn   = w >> 2;
    const int g    = lane >> 2, t4 = lane & 3;

    const int crow = tid >> 1, ch = tid & 1;
    const bool aval = (bm + crow) < M;
    const __half* agp = A  + (size_t)(bm + crow) * K + ch * 8;
    const __half* bgp = Wt + (size_t)(bn + crow) * K + ch * 8;
    const bool bv = (tid < 2 * BN);

    uint32_t a_s = (uint32_t)__cvta_generic_to_shared(&As[0][crow][ch * 4]);
    uint32_t b_s = (uint32_t)__cvta_generic_to_shared(&Bs[0][crow][ch * 4]);
    constexpr uint32_t ASTRIDE = 128 * 12 * 4;
    constexpr uint32_t BSTRIDE = BN * 12 * 4;

#define ISSUE(S, K0)                                                   \
    do {                                                               \
        cpa16(a_s + (S) * ASTRIDE, agp + (K0), aval);                  \
        if (bv) cpa16(b_s + (S) * BSTRIDE, bgp + (K0), true);          \
        asm volatile("cp.async.commit_group;");                        \
    } while (0)

    float acc[2][NT][4];
#pragma unroll
    for (int i = 0; i < 2; i++)
#pragma unroll
        for (int j = 0; j < NT; j++)
#pragma unroll
            for (int r = 0; r < 4; r++) acc[i][j][r] = 0.0f;

    const int kiter = K >> 4;
    ISSUE(0, 0);
    ISSUE(1, 16);
    ISSUE(2, 32);

    const int rm0 = wm * 32;
    const int cn0 = wn * NT * 8;

    for (int it = 0; it < kiter; it++) {
        asm volatile("cp.async.wait_group 2;");
        __syncthreads();
        const int buf = it & 3;
        {
            uint32_t af0[4], af1[4];
            af0[0] = As[buf][rm0 + g][t4];
            af0[1] = As[buf][rm0 + g + 8][t4];
            af0[2] = As[buf][rm0 + g][t4 + 4];
            af0[3] = As[buf][rm0 + g + 8][t4 + 4];
            af1[0] = As[buf][rm0 + 16 + g][t4];
            af1[1] = As[buf][rm0 + 16 + g + 8][t4];
            af1[2] = As[buf][rm0 + 16 + g][t4 + 4];
            af1[3] = As[buf][rm0 + 16 + g + 8][t4 + 4];
            uint32_t bf[NT][2];
#pragma unroll
            for (int j = 0; j < NT; j++) {
                int col = cn0 + j * 8 + g;
                bf[j][0] = Bs[buf][col][t4];
                bf[j][1] = Bs[buf][col][t4 + 4];
            }
#pragma unroll
            for (int j = 0; j < NT; j++) {
                mma16(acc[0][j], af0, bf[j]);
                mma16(acc[1][j], af1, bf[j]);
            }
        }
        __syncthreads();
        if (it + 3 < kiter) ISSUE((it + 3) & 3, (it + 3) * 16);
        else asm volatile("cp.async.commit_group;");
    }
#undef ISSUE

    // ---- epilogue: base cols -> fp16, comb cols -> fp32 + bias ----
#pragma unroll
    for (int i = 0; i < 2; i++) {
        int r0 = bm + rm0 + i * 16 + g;
#pragma unroll
        for (int j = 0; j < NT; j++) {
            int col = bn + cn0 + j * 8 + 2 * t4;
            if (col >= Ntot) continue;
            if (col < NBF) {
                if (r0 < M) {
                    __half2 h = __floats2half2_rn(acc[i][j][0], acc[i][j][1]);
                    *reinterpret_cast<__half2*>(&Ch[(size_t)r0 * NBF + col]) = h;
                }
                if (r0 + 8 < M) {
                    __half2 h = __floats2half2_rn(acc[i][j][2], acc[i][j][3]);
                    *reinterpret_cast<__half2*>(&Ch[(size_t)(r0 + 8) * NBF + col]) = h;
                }
            } else {
                int cc = col - NBF;
                float b0 = bc[cc], b1 = bc[cc + 1];
                if (r0 < M) {
                    float2 v = make_float2(acc[i][j][0] + b0, acc[i][j][1] + b1);
                    *reinterpret_cast<float2*>(&Cc[(size_t)r0 * 96 + cc]) = v;
                }
                if (r0 + 8 < M) {
                    float2 v = make_float2(acc[i][j][2] + b0, acc[i][j][3] + b1);
                    *reinterpret_cast<float2*>(&Cc[(size_t)(r0 + 8) * 96 + cc]) = v;
                }
            }
        }
    }
}

// ---------------- fused aggregation + combine + bias (+relu / +log_softmax) --
__device__ __forceinline__ float4 h4f(uint2 u) {
    __half2 a = *reinterpret_cast<__half2*>(&u.x);
    __half2 b = *reinterpret_cast<__half2*>(&u.y);
    float2 fa = __half22float2(a), fb = __half22float2(b);
    return make_float4(fa.x, fa.y, fb.x, fb.y);
}

// LSM=false: out is __half* [N, 8F].  LSM=true: out is float* [N, OUTT].
template<int NBF, int F, bool RELU, bool LSM>
__global__ __launch_bounds__(256)
void k_agg(const __half* __restrict__ linh, const float* __restrict__ linc,
           const float* __restrict__ bias, void* __restrict__ out_v, int n)
{
    constexpr int HF  = 8 * F;
    constexpr int NI  = HF / 32;
    constexpr int NH4 = NBF / 4;            // uint2 (4-half) slots per row
    constexpr int C4  = (NH4 + 31) / 32;
    __shared__ float agg_s[8][3 * NBF];
    __shared__ float comb_s[8][96];

    int gw   = (blockIdx.x * 256 + threadIdx.x) >> 5;
    int lane = threadIdx.x & 31;
    int lw   = threadIdx.x >> 5;
    if (gw >= n) return;

    int s = g_off[gw], e = g_off[gw + 1];
    int deg = e - s;

    float4 vsym[C4], vsum[C4], vmax[C4];
#pragma unroll
    for (int q = 0; q < C4; q++) {
        vsym[q] = make_float4(0.f, 0.f, 0.f, 0.f);
        vsum[q] = make_float4(0.f, 0.f, 0.f, 0.f);
        vmax[q] = make_float4(-INFINITY, -INFINITY, -INFINITY, -INFINITY);
    }

    int t = s;
    for (; t + 4 <= e; t += 4) {
        int c0 = g_adj[t], c1 = g_adj[t + 1], c2 = g_adj[t + 2], c3 = g_adj[t + 3];
        float d0 = g_dinv[c0], d1 = g_dinv[c1], d2 = g_dinv[c2], d3 = g_dinv[c3];
        const uint2* s0 = reinterpret_cast<const uint2*>(linh + (size_t)c0 * NBF);
        const uint2* s1 = reinterpret_cast<const uint2*>(linh + (size_t)c1 * NBF);
        const uint2* s2 = reinterpret_cast<const uint2*>(linh + (size_t)c2 * NBF);
        const uint2* s3 = reinterpret_cast<const uint2*>(linh + (size_t)c3 * NBF);
#pragma unroll
        for (int q = 0; q < C4; q++) {
            int i4 = lane + q * 32;
            if (C4 > 1 && i4 >= NH4) break;
            float4 v0 = h4f(s0[i4]), v1 = h4f(s1[i4]);
            float4 v2 = h4f(s2[i4]), v3 = h4f(s3[i4]);
            vsym[q].x += (d0 * v0.x + d1 * v1.x) + (d2 * v2.x + d3 * v3.x);
            vsym[q].y += (d0 * v0.y + d1 * v1.y) + (d2 * v2.y + d3 * v3.y);
            vsym[q].z += (d0 * v0.z + d1 * v1.z) + (d2 * v2.z + d3 * v3.z);
            vsym[q].w += (d0 * v0.w + d1 * v1.w) + (d2 * v2.w + d3 * v3.w);
            vsum[q].x += (v0.x + v1.x) + (v2.x + v3.x);
            vsum[q].y += (v0.y + v1.y) + (v2.y + v3.y);
            vsum[q].z += (v0.z + v1.z) + (v2.z + v3.z);
            vsum[q].w += (v0.w + v1.w) + (v2.w + v3.w);
            vmax[q].x = fmaxf(vmax[q].x, fmaxf(fmaxf(v0.x, v1.x), fmaxf(v2.x, v3.x)));
            vmax[q].y = fmaxf(vmax[q].y, fmaxf(fmaxf(v0.y, v1.y), fmaxf(v2.y, v3.y)));
            vmax[q].z = fmaxf(vmax[q].z, fmaxf(fmaxf(v0.z, v1.z), fmaxf(v2.z, v3.z)));
            vmax[q].w = fmaxf(vmax[q].w, fmaxf(fmaxf(v0.w, v1.w), fmaxf(v2.w, v3.w)));
        }
    }
    for (; t < e; t++) {
        int c0 = g_adj[t];
        float d0 = g_dinv[c0];
        const uint2* s0 = reinterpret_cast<const uint2*>(linh + (size_t)c0 * NBF);
#pragma unroll
        for (int q = 0; q < C4; q++) {
            int i4 = lane + q * 32;
            if (C4 > 1 && i4 >= NH4) break;
            float4 v0 = h4f(s0[i4]);
            vsym[q].x += d0 * v0.x; vsym[q].y += d0 * v0.y;
            vsym[q].z += d0 * v0.z; vsym[q].w += d0 * v0.w;
            vsum[q].x += v0.x; vsum[q].y += v0.y;
            vsum[q].z += v0.z; vsum[q].w += v0.w;
            vmax[q].x = fmaxf(vmax[q].x, v0.x); vmax[q].y = fmaxf(vmax[q].y, v0.y);
            vmax[q].z = fmaxf(vmax[q].z, v0.z); vmax[q].w = fmaxf(vmax[q].w, v0.w);
        }
    }

    float dn   = g_dinv[gw];
    float invd = (deg > 0) ? (1.0f / (float)deg) : 0.0f;

    float4* arow0 = reinterpret_cast<float4*>(&agg_s[lw][0]);
    float4* arow1 = reinterpret_cast<float4*>(&agg_s[lw][NBF]);
    float4* arow2 = reinterpret_cast<float4*>(&agg_s[lw][2 * NBF]);
#pragma unroll
    for (int q = 0; q < C4; q++) {
        int i4 = lane + q * 32;
        if (C4 > 1 && i4 >= NH4) break;
        float4 sy = vsym[q];
        sy.x *= dn; sy.y *= dn; sy.z *= dn; sy.w *= dn;
        float4 me = vsum[q];
        me.x *= invd; me.y *= invd; me.z *= invd; me.w *= invd;
        float4 mx = vmax[q];
        if (deg == 0) mx = make_float4(0.f, 0.f, 0.f, 0.f);
        arow0[i4] = sy;
        arow1[i4] = me;
        arow2[i4] = mx;
    }

    const float* comb = linc + (size_t)gw * 96;
    comb_s[lw][lane]      = comb[lane];
    comb_s[lw][lane + 32] = comb[lane + 32];
    comb_s[lw][lane + 64] = comb[lane + 64];
    __syncwarp();

    float vals[NI];
#pragma unroll
    for (int i = 0; i < NI; i++) {
        int c = lane + i * 32;
        int h = c / F, f = c % F;
        float v = bias[c];
        const float* cb = &comb_s[lw][h * 12];
        const float* ag = &agg_s[lw][0];
#pragma unroll
        for (int k = 0; k < 12; k++) v = fmaf(cb[k], ag[k * F + f], v);
        if (RELU) v = fmaxf(v, 0.0f);
        vals[i] = v;
    }

    if (!LSM) {
        __half* out = (__half*)out_v;
#pragma unroll
        for (int i = 0; i < NI; i++)
            out[(size_t)gw * HF + lane + i * 32] = __float2half_rn(vals[i]);
    } else {
        float* out = (float*)out_v;
        float m = -INFINITY;
#pragma unroll
        for (int i = 0; i < NI; i++) {
            int c = lane + i * 32;
            m = fmaxf(m, (c < OUTT) ? vals[i] : -INFINITY);
        }
#pragma unroll
        for (int o = 16; o; o >>= 1) m = fmaxf(m, __shfl_xor_sync(0xffffffffu, m, o));
        float sum = 0.0f;
#pragma unroll
        for (int i = 0; i < NI; i++) {
            int c = lane + i * 32;
            if (c < OUTT) sum += expf(vals[i] - m);
        }
#pragma unroll
        for (int o = 16; o; o >>= 1) sum += __shfl_xor_sync(0xffffffffu, sum, o);
        float l = m + logf(sum);
#pragma unroll
        for (int i = 0; i < NI; i++) {
            int c = lane + i * 32;
            if (c < OUTT) out[(size_t)gw * OUTT + c] = vals[i] - l;
        }
    }
}

// ---------------- launch --------------------------------------------------------
extern "C" void kernel_launch(void* const* d_in, const int* in_sizes, int n_in,
                              void* d_out, int out_size)
{
    const float* x   = (const float*)d_in[0];
    const int*   ei  = (const int*)d_in[1];
    int N = in_sizes[0] / 128;
    int E = in_sizes[1] / 2;
    if (N > NMAX) N = NMAX;
    if (E > EMAX) E = EMAX;
    const int* row = ei;
    const int* col = ei + E;

    const float* Wb0 = (const float*)d_in[2];
    const float* Wc0 = (const float*)d_in[3];
    const float* bc0 = (const float*)d_in[4];
    const float* b0  = (const float*)d_in[5];
    const float* Wb1 = (const float*)d_in[6];
    const float* Wc1 = (const float*)d_in[7];
    const float* bc1 = (const float*)d_in[8];
    const float* b1  = (const float*)d_in[9];
    const float* Wb2 = (const float*)d_in[10];
    const float* Wc2 = (const float*)d_in[11];
    const float* bc2 = (const float*)d_in[12];
    const float* b2  = (const float*)d_in[13];

    __half* linh; float* linc; __half* xh; __half* hA; __half* hB;
    __half* wt0; __half* wt1; __half* wt2;
    cudaGetSymbolAddress((void**)&linh, g_linh);
    cudaGetSymbolAddress((void**)&linc, g_linc);
    cudaGetSymbolAddress((void**)&xh,   g_xh);
    cudaGetSymbolAddress((void**)&hA,   g_hA);
    cudaGetSymbolAddress((void**)&hB,   g_hB);
    cudaGetSymbolAddress((void**)&wt0,  g_wt0);
    cudaGetSymbolAddress((void**)&wt1,  g_wt1);
    cudaGetSymbolAddress((void**)&wt2,  g_wt2);

    const int T  = 256;
    const int gy = (N + 127) / 128;
    const int ab = (N + 7) / 8;
    const int sb = (N + 255) / 256;
    const int n4 = N * 128 / 4;

    k_cvt_x<<<(n4 + T - 1) / T, T>>>(x, (__half2*)xh, n4);
    k_cvt_w<<<(224 * 128 + T - 1) / T, T>>>(Wb0, Wc0, wt0, 128, 128, 224, 224);
    k_cvt_w<<<(224 * 256 + T - 1) / T, T>>>(Wb1, Wc1, wt1, 256, 128, 224, 224);
    k_cvt_w<<<(288 * 256 + T - 1) / T, T>>>(Wb2, Wc2, wt2, 256, 176, 272, 288);
    k_zero   <<<(N + T - 1) / T, T>>>(N);
    k_deg    <<<(E + T - 1) / T, T>>>(row, E);
    k_dinv   <<<(N + T - 1) / T, T>>>(N);
    k_gemm_h<7><<<dim3(2, gy), 256>>>(xh, wt0, bc0, linh, linc, N, 128, 128, 224);
    k_scan1  <<<sb, 256>>>(N);
    k_scan2  <<<1, 256>>>(sb);
    k_scan3  <<<sb, 256>>>(N, E);
    k_scatter<<<(E + T - 1) / T, T>>>(row, col, E);

    k_agg<128, 32, true, false><<<ab, 256>>>(linh, linc, b0, hA, N);

    k_gemm_h<7><<<dim3(2, gy), 256>>>(hA, wt1, bc1, linh, linc, N, 256, 128, 224);
    k_agg<128, 32, true, false><<<ab, 256>>>(linh, linc, b1, hB, N);

    k_gemm_h<6><<<dim3(3, gy), 256>>>(hB, wt2, bc2, linh, linc, N, 256, 176, 272);
    k_agg<176, 44, false, true><<<ab, 256>>>(linh, linc, b2, d_out, N);
}

// round 8
// speedup vs baseline: 1.3495x; 1.0302x over previous
#include <cuda_runtime.h>
#include <cuda_fp16.h>
#include <math.h>
#include <stdint.h>

#define NMAX   50000
#define EMAX   600000
#define OUTT   349

// ---------------- scratch (device globals) ----------------------------------
__device__ int    g_deg[NMAX];
__device__ float  g_dinv[NMAX];
__device__ int    g_off[NMAX + 1];
__device__ int    g_cur[NMAX];
__device__ int    g_adj[EMAX];
__device__ float  g_adjd[EMAX];
__device__ int    g_bsum[256];
__device__ __half g_linh[(size_t)NMAX * 176];   // bases (fp16), pitch = NBF
__device__ float  g_linc[(size_t)NMAX * 96];    // comb (fp32), pitch = 96
__device__ __half g_xh[(size_t)NMAX * 128];
__device__ __half g_hA[(size_t)NMAX * 256];
__device__ __half g_hB[(size_t)NMAX * 256];
__device__ __half g_wt0[224 * 128];
__device__ __half g_wt1[224 * 256];
__device__ __half g_wt2[288 * 256];

// ---------------- converts ----------------------------------------------------
__global__ void k_cvt_x(const float* __restrict__ x, __half2* __restrict__ xh, int n4) {
    int i = blockIdx.x * blockDim.x + threadIdx.x;
    if (i < n4) {
        float4 v = reinterpret_cast<const float4*>(x)[i];
        xh[2 * i]     = __floats2half2_rn(v.x, v.y);
        xh[2 * i + 1] = __floats2half2_rn(v.z, v.w);
    }
}

__device__ __forceinline__ void cvt_one(const float* Wb, const float* Wc, __half* Wt,
                                        int idx, int K, int NBF, int Ntot) {
    int n = idx / K, k = idx % K;
    float v = 0.0f;
    if (n < NBF)       v = Wb[k * NBF + n];
    else if (n < Ntot) v = Wc[k * (Ntot - NBF) + (n - NBF)];
    Wt[idx] = __float2half_rn(v);
}

// one kernel converts all three fused-transposed weight matrices
__global__ void k_cvt_wall(const float* __restrict__ Wb0, const float* __restrict__ Wc0,
                           const float* __restrict__ Wb1, const float* __restrict__ Wc1,
                           const float* __restrict__ Wb2, const float* __restrict__ Wc2,
                           __half* __restrict__ wt0, __half* __restrict__ wt1,
                           __half* __restrict__ wt2) {
    const int S0 = 224 * 128, S1 = 224 * 256, S2 = 288 * 256;
    int idx = blockIdx.x * blockDim.x + threadIdx.x;
    if (idx < S0)                cvt_one(Wb0, Wc0, wt0, idx,            128, 128, 224);
    else if (idx < S0 + S1)      cvt_one(Wb1, Wc1, wt1, idx - S0,       256, 128, 224);
    else if (idx < S0 + S1 + S2) cvt_one(Wb2, Wc2, wt2, idx - S0 - S1,  256, 176, 272);
}

// ---------------- CSR build --------------------------------------------------
__global__ void k_zero(int n) {
    int i = blockIdx.x * blockDim.x + threadIdx.x;
    if (i < n) g_deg[i] = 0;
}

__global__ void k_deg(const int* __restrict__ row, int e) {
    int i = blockIdx.x * blockDim.x + threadIdx.x;
    if (i < e) atomicAdd(&g_deg[row[i]], 1);
}

// block partial sums + dinv (fused)
__global__ void k_scan1(int n) {
    __shared__ int sh[256];
    int t = threadIdx.x;
    int i = blockIdx.x * 256 + t;
    int d = (i < n) ? g_deg[i] : 0;
    sh[t] = d;
    if (i < n) g_dinv[i] = (d > 0) ? rsqrtf((float)d) : 0.0f;
    __syncthreads();
#pragma unroll
    for (int s = 128; s; s >>= 1) {
        if (t < s) sh[t] += sh[t + s];
        __syncthreads();
    }
    if (t == 0) g_bsum[blockIdx.x] = sh[0];
}

__global__ void k_scan2(int nb) {
    __shared__ int sh[256];
    int t = threadIdx.x;
    int v = (t < nb) ? g_bsum[t] : 0;
    sh[t] = v;
    __syncthreads();
#pragma unroll
    for (int d = 1; d < 256; d <<= 1) {
        int u = (t >= d) ? sh[t - d] : 0;
        __syncthreads();
        sh[t] += u;
        __syncthreads();
    }
    if (t < nb) g_bsum[t] = sh[t] - v;
}

__global__ void k_scan3(int n, int total) {
    __shared__ int sh[256];
    int t = threadIdx.x;
    int i = blockIdx.x * 256 + t;
    int v = (i < n) ? g_deg[i] : 0;
    sh[t] = v;
    __syncthreads();
#pragma unroll
    for (int d = 1; d < 256; d <<= 1) {
        int u = (t >= d) ? sh[t - d] : 0;
        __syncthreads();
        sh[t] += u;
        __syncthreads();
    }
    int excl = sh[t] - v + g_bsum[blockIdx.x];
    if (i < n) { g_off[i] = excl; g_cur[i] = excl; }
    if (blockIdx.x == 0 && t == 0) g_off[n] = total;
}

// scatter col index AND its dinv (so agg reads norm coalesced, not via a
// dependent random load)
__global__ void k_scatter(const int* __restrict__ row, const int* __restrict__ col, int e) {
    int i = blockIdx.x * blockDim.x + threadIdx.x;
    if (i < e) {
        int r = row[i];
        int c = col[i];
        int p = atomicAdd(&g_cur[r], 1);
        g_adj[p]  = c;
        g_adjd[p] = g_dinv[c];
    }
}

// ---------------- fp16 tensor-core GEMM, cp.async 4-stage pipeline ------------
__device__ __forceinline__ void mma16(float* c, const uint32_t* a, const uint32_t* b) {
    asm volatile(
        "mma.sync.aligned.m16n8k16.row.col.f32.f16.f16.f32 "
        "{%0,%1,%2,%3}, {%4,%5,%6,%7}, {%8,%9}, {%0,%1,%2,%3};"
        : "+f"(c[0]), "+f"(c[1]), "+f"(c[2]), "+f"(c[3])
        : "r"(a[0]), "r"(a[1]), "r"(a[2]), "r"(a[3]), "r"(b[0]), "r"(b[1]));
}

__device__ __forceinline__ void cpa16(uint32_t saddr, const void* gptr, bool pred) {
    int sz = pred ? 16 : 0;
    asm volatile("cp.async.ca.shared.global [%0], [%1], 16, %2;"
                 :: "r"(saddr), "l"(gptr), "r"(sz));
}

template<int NT>
__global__ __launch_bounds__(256)
void k_gemm_h(const __half* __restrict__ A, const __half* __restrict__ Wt,
              const float* __restrict__ bc,
              __half* __restrict__ Ch, float* __restrict__ Cc,
              int M, int K, int NBF, int Ntot)
{
    constexpr int BN = 16 * NT;
    __shared__ __align__(16) uint32_t As[4][128][12];
    __shared__ __align__(16) uint32_t Bs[4][BN][12];

    const int tid  = threadIdx.x;
    const int bm   = blockIdx.y * 128;
    const int bn   = blockIdx.x * BN;
    const int w    = tid >> 5, lane = tid & 31;
    const int wm   = w & 3,   wn   = w >> 2;
    const int g    = lane >> 2, t4 = lane & 3;

    const int crow = tid >> 1, ch = tid & 1;
    const bool aval = (bm + crow) < M;
    const __half* agp = A  + (size_t)(bm + crow) * K + ch * 8;
    const __half* bgp = Wt + (size_t)(bn + crow) * K + ch * 8;
    const bool bv = (tid < 2 * BN);

    uint32_t a_s = (uint32_t)__cvta_generic_to_shared(&As[0][crow][ch * 4]);
    uint32_t b_s = (uint32_t)__cvta_generic_to_shared(&Bs[0][crow][ch * 4]);
    constexpr uint32_t ASTRIDE = 128 * 12 * 4;
    constexpr uint32_t BSTRIDE = BN * 12 * 4;

#define ISSUE(S, K0)                                                   \
    do {                                                               \
        cpa16(a_s + (S) * ASTRIDE, agp + (K0), aval);                  \
        if (bv) cpa16(b_s + (S) * BSTRIDE, bgp + (K0), true);          \
        asm volatile("cp.async.commit_group;");                        \
    } while (0)

    float acc[2][NT][4];
#pragma unroll
    for (int i = 0; i < 2; i++)
#pragma unroll
        for (int j = 0; j < NT; j++)
#pragma unroll
            for (int r = 0; r < 4; r++) acc[i][j][r] = 0.0f;

    const int kiter = K >> 4;
    ISSUE(0, 0);
    ISSUE(1, 16);
    ISSUE(2, 32);

    const int rm0 = wm * 32;
    const int cn0 = wn * NT * 8;

    for (int it = 0; it < kiter; it++) {
        asm volatile("cp.async.wait_group 2;");
        __syncthreads();
        const int buf = it & 3;
        {
            uint32_t af0[4], af1[4];
            af0[0] = As[buf][rm0 + g][t4];
            af0[1] = As[buf][rm0 + g + 8][t4];
            af0[2] = As[buf][rm0 + g][t4 + 4];
            af0[3] = As[buf][rm0 + g + 8][t4 + 4];
            af1[0] = As[buf][rm0 + 16 + g][t4];
            af1[1] = As[buf][rm0 + 16 + g + 8][t4];
            af1[2] = As[buf][rm0 + 16 + g][t4 + 4];
            af1[3] = As[buf][rm0 + 16 + g + 8][t4 + 4];
            uint32_t bf[NT][2];
#pragma unroll
            for (int j = 0; j < NT; j++) {
                int col = cn0 + j * 8 + g;
                bf[j][0] = Bs[buf][col][t4];
                bf[j][1] = Bs[buf][col][t4 + 4];
            }
#pragma unroll
            for (int j = 0; j < NT; j++) {
                mma16(acc[0][j], af0, bf[j]);
                mma16(acc[1][j], af1, bf[j]);
            }
        }
        __syncthreads();
        if (it + 3 < kiter) ISSUE((it + 3) & 3, (it + 3) * 16);
        else asm volatile("cp.async.commit_group;");
    }
#undef ISSUE

    // ---- epilogue: base cols -> fp16, comb cols -> fp32 + bias ----
#pragma unroll
    for (int i = 0; i < 2; i++) {
        int r0 = bm + rm0 + i * 16 + g;
#pragma unroll
        for (int j = 0; j < NT; j++) {
            int col = bn + cn0 + j * 8 + 2 * t4;
            if (col >= Ntot) continue;
            if (col < NBF) {
                if (r0 < M) {
                    __half2 h = __floats2half2_rn(acc[i][j][0], acc[i][j][1]);
                    *reinterpret_cast<__half2*>(&Ch[(size_t)r0 * NBF + col]) = h;
                }
                if (r0 + 8 < M) {
                    __half2 h = __floats2half2_rn(acc[i][j][2], acc[i][j][3]);
                    *reinterpret_cast<__half2*>(&Ch[(size_t)(r0 + 8) * NBF + col]) = h;
                }
            } else {
                int cc = col - NBF;
                float b0 = bc[cc], b1 = bc[cc + 1];
                if (r0 < M) {
                    float2 v = make_float2(acc[i][j][0] + b0, acc[i][j][1] + b1);
                    *reinterpret_cast<float2*>(&Cc[(size_t)r0 * 96 + cc]) = v;
                }
                if (r0 + 8 < M) {
                    float2 v = make_float2(acc[i][j][2] + b0, acc[i][j][3] + b1);
                    *reinterpret_cast<float2*>(&Cc[(size_t)(r0 + 8) * 96 + cc]) = v;
                }
            }
        }
    }
}

// ---------------- fused aggregation + combine + bias (+relu / +log_softmax) --
__device__ __forceinline__ float4 h4f(uint2 u) {
    __half2 a = *reinterpret_cast<__half2*>(&u.x);
    __half2 b = *reinterpret_cast<__half2*>(&u.y);
    float2 fa = __half22float2(a), fb = __half22float2(b);
    return make_float4(fa.x, fa.y, fb.x, fb.y);
}

template<int NBF, int F, bool RELU, bool LSM>
__global__ __launch_bounds__(256)
void k_agg(const __half* __restrict__ linh, const float* __restrict__ linc,
           const float* __restrict__ bias, void* __restrict__ out_v, int n)
{
    constexpr int HF  = 8 * F;
    constexpr int NI  = HF / 32;
    constexpr int NH4 = NBF / 4;
    constexpr int C4  = (NH4 + 31) / 32;
    __shared__ float agg_s[8][3 * NBF];
    __shared__ float comb_s[8][96];

    int gw   = (blockIdx.x * 256 + threadIdx.x) >> 5;
    int lane = threadIdx.x & 31;
    int lw   = threadIdx.x >> 5;
    if (gw >= n) return;

    int s = g_off[gw], e = g_off[gw + 1];
    int deg = e - s;

    float4 vsym[C4], vsum[C4], vmax[C4];
#pragma unroll
    for (int q = 0; q < C4; q++) {
        vsym[q] = make_float4(0.f, 0.f, 0.f, 0.f);
        vsum[q] = make_float4(0.f, 0.f, 0.f, 0.f);
        vmax[q] = make_float4(-INFINITY, -INFINITY, -INFINITY, -INFINITY);
    }

    int t = s;
    for (; t + 4 <= e; t += 4) {
        int c0 = g_adj[t], c1 = g_adj[t + 1], c2 = g_adj[t + 2], c3 = g_adj[t + 3];
        float d0 = g_adjd[t],     d1 = g_adjd[t + 1];
        float d2 = g_adjd[t + 2], d3 = g_adjd[t + 3];
        const uint2* s0 = reinterpret_cast<const uint2*>(linh + (size_t)c0 * NBF);
        const uint2* s1 = reinterpret_cast<const uint2*>(linh + (size_t)c1 * NBF);
        const uint2* s2 = reinterpret_cast<const uint2*>(linh + (size_t)c2 * NBF);
        const uint2* s3 = reinterpret_cast<const uint2*>(linh + (size_t)c3 * NBF);
#pragma unroll
        for (int q = 0; q < C4; q++) {
            int i4 = lane + q * 32;
            if (C4 > 1 && i4 >= NH4) break;
            float4 v0 = h4f(s0[i4]), v1 = h4f(s1[i4]);
            float4 v2 = h4f(s2[i4]), v3 = h4f(s3[i4]);
            vsym[q].x += (d0 * v0.x + d1 * v1.x) + (d2 * v2.x + d3 * v3.x);
            vsym[q].y += (d0 * v0.y + d1 * v1.y) + (d2 * v2.y + d3 * v3.y);
            vsym[q].z += (d0 * v0.z + d1 * v1.z) + (d2 * v2.z + d3 * v3.z);
            vsym[q].w += (d0 * v0.w + d1 * v1.w) + (d2 * v2.w + d3 * v3.w);
            vsum[q].x += (v0.x + v1.x) + (v2.x + v3.x);
            vsum[q].y += (v0.y + v1.y) + (v2.y + v3.y);
            vsum[q].z += (v0.z + v1.z) + (v2.z + v3.z);
            vsum[q].w += (v0.w + v1.w) + (v2.w + v3.w);
            vmax[q].x = fmaxf(vmax[q].x, fmaxf(fmaxf(v0.x, v1.x), fmaxf(v2.x, v3.x)));
            vmax[q].y = fmaxf(vmax[q].y, fmaxf(fmaxf(v0.y, v1.y), fmaxf(v2.y, v3.y)));
            vmax[q].z = fmaxf(vmax[q].z, fmaxf(fmaxf(v0.z, v1.z), fmaxf(v2.z, v3.z)));
            vmax[q].w = fmaxf(vmax[q].w, fmaxf(fmaxf(v0.w, v1.w), fmaxf(v2.w, v3.w)));
        }
    }
    for (; t < e; t++) {
        int c0 = g_adj[t];
        float d0 = g_adjd[t];
        const uint2* s0 = reinterpret_cast<const uint2*>(linh + (size_t)c0 * NBF);
#pragma unroll
        for (int q = 0; q < C4; q++) {
            int i4 = lane + q * 32;
            if (C4 > 1 && i4 >= NH4) break;
            float4 v0 = h4f(s0[i4]);
            vsym[q].x += d0 * v0.x; vsym[q].y += d0 * v0.y;
            vsym[q].z += d0 * v0.z; vsym[q].w += d0 * v0.w;
            vsum[q].x += v0.x; vsum[q].y += v0.y;
            vsum[q].z += v0.z; vsum[q].w += v0.w;
            vmax[q].x = fmaxf(vmax[q].x, v0.x); vmax[q].y = fmaxf(vmax[q].y, v0.y);
            vmax[q].z = fmaxf(vmax[q].z, v0.z); vmax[q].w = fmaxf(vmax[q].w, v0.w);
        }
    }

    float dn   = g_dinv[gw];
    float invd = (deg > 0) ? (1.0f / (float)deg) : 0.0f;

    float4* arow0 = reinterpret_cast<float4*>(&agg_s[lw][0]);
    float4* arow1 = reinterpret_cast<float4*>(&agg_s[lw][NBF]);
    float4* arow2 = reinterpret_cast<float4*>(&agg_s[lw][2 * NBF]);
#pragma unroll
    for (int q = 0; q < C4; q++) {
        int i4 = lane + q * 32;
        if (C4 > 1 && i4 >= NH4) break;
        float4 sy = vsym[q];
        sy.x *= dn; sy.y *= dn; sy.z *= dn; sy.w *= dn;
        float4 me = vsum[q];
        me.x *= invd; me.y *= invd; me.z *= invd; me.w *= invd;
        float4 mx = vmax[q];
        if (deg == 0) mx = make_float4(0.f, 0.f, 0.f, 0.f);
        arow0[i4] = sy;
        arow1[i4] = me;
        arow2[i4] = mx;
    }

    const float* comb = linc + (size_t)gw * 96;
    comb_s[lw][lane]      = comb[lane];
    comb_s[lw][lane + 32] = comb[lane + 32];
    comb_s[lw][lane + 64] = comb[lane + 64];
    __syncwarp();

    float vals[NI];
#pragma unroll
    for (int i = 0; i < NI; i++) {
        int c = lane + i * 32;
        int h = c / F, f = c % F;
        float v = bias[c];
        const float* cb = &comb_s[lw][h * 12];
        const float* ag = &agg_s[lw][0];
#pragma unroll
        for (int k = 0; k < 12; k++) v = fmaf(cb[k], ag[k * F + f], v);
        if (RELU) v = fmaxf(v, 0.0f);
        vals[i] = v;
    }

    if (!LSM) {
        __half* out = (__half*)out_v;
#pragma unroll
        for (int i = 0; i < NI; i++)
            out[(size_t)gw * HF + lane + i * 32] = __float2half_rn(vals[i]);
    } else {
        float* out = (float*)out_v;
        float m = -INFINITY;
#pragma unroll
        for (int i = 0; i < NI; i++) {
            int c = lane + i * 32;
            m = fmaxf(m, (c < OUTT) ? vals[i] : -INFINITY);
        }
#pragma unroll
        for (int o = 16; o; o >>= 1) m = fmaxf(m, __shfl_xor_sync(0xffffffffu, m, o));
        float sum = 0.0f;
#pragma unroll
        for (int i = 0; i < NI; i++) {
            int c = lane + i * 32;
            if (c < OUTT) sum += expf(vals[i] - m);
        }
#pragma unroll
        for (int o = 16; o; o >>= 1) sum += __shfl_xor_sync(0xffffffffu, sum, o);
        float l = m + logf(sum);
#pragma unroll
        for (int i = 0; i < NI; i++) {
            int c = lane + i * 32;
            if (c < OUTT) out[(size_t)gw * OUTT + c] = vals[i] - l;
        }
    }
}

// ---------------- launch --------------------------------------------------------
extern "C" void kernel_launch(void* const* d_in, const int* in_sizes, int n_in,
                              void* d_out, int out_size)
{
    const float* x   = (const float*)d_in[0];
    const int*   ei  = (const int*)d_in[1];
    int N = in_sizes[0] / 128;
    int E = in_sizes[1] / 2;
    if (N > NMAX) N = NMAX;
    if (E > EMAX) E = EMAX;
    const int* row = ei;
    const int* col = ei + E;

    const float* Wb0 = (const float*)d_in[2];
    const float* Wc0 = (const float*)d_in[3];
    const float* bc0 = (const float*)d_in[4];
    const float* b0  = (const float*)d_in[5];
    const float* Wb1 = (const float*)d_in[6];
    const float* Wc1 = (const float*)d_in[7];
    const float* bc1 = (const float*)d_in[8];
    const float* b1  = (const float*)d_in[9];
    const float* Wb2 = (const float*)d_in[10];
    const float* Wc2 = (const float*)d_in[11];
    const float* bc2 = (const float*)d_in[12];
    const float* b2  = (const float*)d_in[13];

    __half* linh; float* linc; __half* xh; __half* hA; __half* hB;
    __half* wt0; __half* wt1; __half* wt2;
    cudaGetSymbolAddress((void**)&linh, g_linh);
    cudaGetSymbolAddress((void**)&linc, g_linc);
    cudaGetSymbolAddress((void**)&xh,   g_xh);
    cudaGetSymbolAddress((void**)&hA,   g_hA);
    cudaGetSymbolAddress((void**)&hB,   g_hB);
    cudaGetSymbolAddress((void**)&wt0,  g_wt0);
    cudaGetSymbolAddress((void**)&wt1,  g_wt1);
    cudaGetSymbolAddress((void**)&wt2,  g_wt2);

    const int T  = 256;
    const int gy = (N + 127) / 128;
    const int ab = (N + 7) / 8;
    const int sb = (N + 255) / 256;
    const int n4 = N * 128 / 4;
    const int WALL = 224 * 128 + 224 * 256 + 288 * 256;

    // Fork: CSR chain on a side stream, converts+GEMM0 on the main stream.
    // (Stream/events created per call; not destroyed — destroying a stream
    //  participating in an active capture invalidates the capture.)
    cudaStream_t s1;
    cudaStreamCreateWithFlags(&s1, cudaStreamNonBlocking);
    cudaEvent_t evRoot, evCsr;
    cudaEventCreateWithFlags(&evRoot, cudaEventDisableTiming);
    cudaEventCreateWithFlags(&evCsr,  cudaEventDisableTiming);

    cudaEventRecord(evRoot, 0);
    cudaStreamWaitEvent(s1, evRoot, 0);

    // side stream: CSR build
    k_zero   <<<(N + T - 1) / T, T, 0, s1>>>(N);
    k_deg    <<<(E + T - 1) / T, T, 0, s1>>>(row, E);
    k_scan1  <<<sb, 256, 0, s1>>>(N);             // + dinv
    k_scan2  <<<1, 256, 0, s1>>>(sb);
    k_scan3  <<<sb, 256, 0, s1>>>(N, E);
    k_scatter<<<(E + T - 1) / T, T, 0, s1>>>(row, col, E);
    cudaEventRecord(evCsr, s1);

    // main stream: converts + layer-0 GEMM (independent of CSR)
    k_cvt_x   <<<(n4 + T - 1) / T, T>>>(x, (__half2*)xh, n4);
    k_cvt_wall<<<(WALL + T - 1) / T, T>>>(Wb0, Wc0, Wb1, Wc1, Wb2, Wc2, wt0, wt1, wt2);
    k_gemm_h<7><<<dim3(2, gy), 256>>>(xh, wt0, bc0, linh, linc, N, 128, 128, 224);

    // join
    cudaStreamWaitEvent(0, evCsr, 0);

    k_agg<128, 32, true, false><<<ab, 256>>>(linh, linc, b0, hA, N);

    k_gemm_h<7><<<dim3(2, gy), 256>>>(hA, wt1, bc1, linh, linc, N, 256, 128, 224);
    k_agg<128, 32, true, false><<<ab, 256>>>(linh, linc, b1, hB, N);

    k_gemm_h<6><<<dim3(3, gy), 256>>>(hB, wt2, bc2, linh, linc, N, 256, 176, 272);
    k_agg<176, 44, false, true><<<ab, 256>>>(linh, linc, b2, d_out, N);
}

// round 9
// speedup vs baseline: 1.4026x; 1.0393x over previous
#include <cuda_runtime.h>
#include <cuda_fp16.h>
#include <math.h>
#include <stdint.h>

#define NMAX   50000
#define EMAX   600000
#define OUTT   349

// ---------------- scratch (device globals) ----------------------------------
__device__ int    g_deg[NMAX];
__device__ float  g_dinv[NMAX];
__device__ int    g_off[NMAX + 1];
__device__ int    g_cur[NMAX];
__device__ int    g_adj[EMAX];
__device__ float  g_adjd[EMAX];
__device__ int    g_bsum[256];
__device__ __half g_linh[(size_t)NMAX * 176];   // bases (fp16), pitch = NBF
__device__ float  g_linc[(size_t)NMAX * 96];    // comb (fp32), pitch = 96
__device__ __half g_xh[(size_t)NMAX * 128];
__device__ __half g_hA[(size_t)NMAX * 256];
__device__ __half g_hB[(size_t)NMAX * 256];
__device__ __half g_wt0[224 * 128];
__device__ __half g_wt1[224 * 256];
__device__ __half g_wt2[288 * 256];

// ---------------- converts ----------------------------------------------------
__global__ void k_cvt_x(const float* __restrict__ x, __half2* __restrict__ xh, int n4) {
    int i = blockIdx.x * blockDim.x + threadIdx.x;
    if (i < n4) {
        float4 v = reinterpret_cast<const float4*>(x)[i];
        xh[2 * i]     = __floats2half2_rn(v.x, v.y);
        xh[2 * i + 1] = __floats2half2_rn(v.z, v.w);
    }
}

__device__ __forceinline__ void cvt_one(const float* Wb, const float* Wc, __half* Wt,
                                        int idx, int K, int NBF, int Ntot) {
    int n = idx / K, k = idx % K;
    float v = 0.0f;
    if (n < NBF)       v = Wb[k * NBF + n];
    else if (n < Ntot) v = Wc[k * (Ntot - NBF) + (n - NBF)];
    Wt[idx] = __float2half_rn(v);
}

__global__ void k_cvt_wall(const float* __restrict__ Wb0, const float* __restrict__ Wc0,
                           const float* __restrict__ Wb1, const float* __restrict__ Wc1,
                           const float* __restrict__ Wb2, const float* __restrict__ Wc2,
                           __half* __restrict__ wt0, __half* __restrict__ wt1,
                           __half* __restrict__ wt2) {
    const int S0 = 224 * 128, S1 = 224 * 256, S2 = 288 * 256;
    int idx = blockIdx.x * blockDim.x + threadIdx.x;
    if (idx < S0)                cvt_one(Wb0, Wc0, wt0, idx,            128, 128, 224);
    else if (idx < S0 + S1)      cvt_one(Wb1, Wc1, wt1, idx - S0,       256, 128, 224);
    else if (idx < S0 + S1 + S2) cvt_one(Wb2, Wc2, wt2, idx - S0 - S1,  256, 176, 272);
}

// ---------------- CSR build --------------------------------------------------
__global__ void k_zero(int n) {
    int i = blockIdx.x * blockDim.x + threadIdx.x;
    if (i < n) g_deg[i] = 0;
}

__global__ void k_deg(const int* __restrict__ row, int e) {
    int i = blockIdx.x * blockDim.x + threadIdx.x;
    if (i < e) atomicAdd(&g_deg[row[i]], 1);
}

__global__ void k_scan1(int n) {
    __shared__ int sh[256];
    int t = threadIdx.x;
    int i = blockIdx.x * 256 + t;
    int d = (i < n) ? g_deg[i] : 0;
    sh[t] = d;
    if (i < n) g_dinv[i] = (d > 0) ? rsqrtf((float)d) : 0.0f;
    __syncthreads();
#pragma unroll
    for (int s = 128; s; s >>= 1) {
        if (t < s) sh[t] += sh[t + s];
        __syncthreads();
    }
    if (t == 0) g_bsum[blockIdx.x] = sh[0];
}

__global__ void k_scan2(int nb) {
    __shared__ int sh[256];
    int t = threadIdx.x;
    int v = (t < nb) ? g_bsum[t] : 0;
    sh[t] = v;
    __syncthreads();
#pragma unroll
    for (int d = 1; d < 256; d <<= 1) {
        int u = (t >= d) ? sh[t - d] : 0;
        __syncthreads();
        sh[t] += u;
        __syncthreads();
    }
    if (t < nb) g_bsum[t] = sh[t] - v;
}

__global__ void k_scan3(int n, int total) {
    __shared__ int sh[256];
    int t = threadIdx.x;
    int i = blockIdx.x * 256 + t;
    int v = (i < n) ? g_deg[i] : 0;
    sh[t] = v;
    __syncthreads();
#pragma unroll
    for (int d = 1; d < 256; d <<= 1) {
        int u = (t >= d) ? sh[t - d] : 0;
        __syncthreads();
        sh[t] += u;
        __syncthreads();
    }
    int excl = sh[t] - v + g_bsum[blockIdx.x];
    if (i < n) { g_off[i] = excl; g_cur[i] = excl; }
    if (blockIdx.x == 0 && t == 0) g_off[n] = total;
}

__global__ void k_scatter(const int* __restrict__ row, const int* __restrict__ col, int e) {
    int i = blockIdx.x * blockDim.x + threadIdx.x;
    if (i < e) {
        int r = row[i];
        int c = col[i];
        int p = atomicAdd(&g_cur[r], 1);
        g_adj[p]  = c;
        g_adjd[p] = g_dinv[c];
    }
}

// ---------------- fp16 tensor-core GEMM, cp.async + ldmatrix ------------------
__device__ __forceinline__ void mma16(float* c, const uint32_t* a, const uint32_t* b) {
    asm volatile(
        "mma.sync.aligned.m16n8k16.row.col.f32.f16.f16.f32 "
        "{%0,%1,%2,%3}, {%4,%5,%6,%7}, {%8,%9}, {%0,%1,%2,%3};"
        : "+f"(c[0]), "+f"(c[1]), "+f"(c[2]), "+f"(c[3])
        : "r"(a[0]), "r"(a[1]), "r"(a[2]), "r"(a[3]), "r"(b[0]), "r"(b[1]));
}

__device__ __forceinline__ void cpa16(uint32_t saddr, const void* gptr, bool pred) {
    int sz = pred ? 16 : 0;
    asm volatile("cp.async.ca.shared.global [%0], [%1], 16, %2;"
                 :: "r"(saddr), "l"(gptr), "r"(sz));
}

__device__ __forceinline__ void ldsm4(uint32_t& a, uint32_t& b, uint32_t& c, uint32_t& d,
                                      uint32_t addr) {
    asm volatile("ldmatrix.sync.aligned.m8n8.x4.shared.b16 {%0,%1,%2,%3}, [%4];"
                 : "=r"(a), "=r"(b), "=r"(c), "=r"(d) : "r"(addr));
}
__device__ __forceinline__ void ldsm2(uint32_t& a, uint32_t& b, uint32_t addr) {
    asm volatile("ldmatrix.sync.aligned.m8n8.x2.shared.b16 {%0,%1}, [%2];"
                 : "=r"(a), "=r"(b) : "r"(addr));
}

// A: [M,K] fp16 K-major.  Wt: [NtotPad,K] fp16 K-major.
// smem rows: 16 halves (8 u32) at pitch 12 u32; ldmatrix fragment loads.
template<int NT>
__global__ __launch_bounds__(256)
void k_gemm_h(const __half* __restrict__ A, const __half* __restrict__ Wt,
              const float* __restrict__ bc,
              __half* __restrict__ Ch, float* __restrict__ Cc,
              int M, int K, int NBF, int Ntot)
{
    constexpr int BN    = 16 * NT;
    constexpr int NPAIR = NT / 2;
    constexpr int TAIL  = NT & 1;
    __shared__ __align__(16) uint32_t As[4][128][12];
    __shared__ __align__(16) uint32_t Bs[4][BN][12];

    const int tid  = threadIdx.x;
    const int bm   = blockIdx.y * 128;
    const int bn   = blockIdx.x * BN;
    const int w    = tid >> 5, lane = tid & 31;
    const int wm   = w & 3,   wn   = w >> 2;
    const int g    = lane >> 2, t4 = lane & 3;

    const int crow = tid >> 1, ch = tid & 1;
    const bool aval = (bm + crow) < M;
    const __half* agp = A  + (size_t)(bm + crow) * K + ch * 8;
    const __half* bgp = Wt + (size_t)(bn + crow) * K + ch * 8;
    const bool bv = (tid < 2 * BN);

    uint32_t a_s = (uint32_t)__cvta_generic_to_shared(&As[0][crow][ch * 4]);
    uint32_t b_s = (uint32_t)__cvta_generic_to_shared(&Bs[0][crow][ch * 4]);
    constexpr uint32_t ASTRIDE = 128 * 12 * 4;
    constexpr uint32_t BSTRIDE = BN * 12 * 4;

    const int rm0 = wm * 32;
    const int cn0 = wn * NT * 8;

    // ---- ldmatrix per-lane addresses (stage 0; add buf*STRIDE later) ----
    // A 16x16 tile at rows rm0(+16): lanes 0-7 tile(r0-7,k0-7), 8-15 (r8-15,k0-7),
    // 16-23 (r0-7,k8-15), 24-31 (r8-15,k8-15).
    const int arow = rm0 + ((lane >> 3) & 1) * 8 + (lane & 7);
    const int awrd = (lane >> 4) * 4;
    const uint32_t sA0 = (uint32_t)__cvta_generic_to_shared(&As[0][arow][awrd]);
    // B pair p covers n-tiles 2p,2p+1: lanes 0-7 (j=2p,k0-7), 8-15 (j=2p,k8-15),
    // 16-23 (j=2p+1,k0-7), 24-31 (j=2p+1,k8-15).
    uint32_t sB[NPAIR + TAIL];
#pragma unroll
    for (int p = 0; p < NPAIR; p++) {
        int brow = cn0 + p * 16 + ((lane >> 4) & 1) * 8 + (lane & 7);
        int bwrd = ((lane >> 3) & 1) * 4;
        sB[p] = (uint32_t)__cvta_generic_to_shared(&Bs[0][brow][bwrd]);
    }
    if (TAIL) {
        int brow = cn0 + NPAIR * 16 + (lane & 7);
        int bwrd = ((lane >> 3) & 1) * 4;
        sB[NPAIR] = (uint32_t)__cvta_generic_to_shared(&Bs[0][brow][bwrd]);
    }

#define ISSUE(S, K0)                                                   \
    do {                                                               \
        cpa16(a_s + (S) * ASTRIDE, agp + (K0), aval);                  \
        if (bv) cpa16(b_s + (S) * BSTRIDE, bgp + (K0), true);          \
        asm volatile("cp.async.commit_group;");                        \
    } while (0)

    float acc[2][NT][4];
#pragma unroll
    for (int i = 0; i < 2; i++)
#pragma unroll
        for (int j = 0; j < NT; j++)
#pragma unroll
            for (int r = 0; r < 4; r++) acc[i][j][r] = 0.0f;

    const int kiter = K >> 4;
    ISSUE(0, 0);
    ISSUE(1, 16);
    ISSUE(2, 32);

    for (int it = 0; it < kiter; it++) {
        asm volatile("cp.async.wait_group 2;");
        __syncthreads();
        const uint32_t aoff = (uint32_t)(it & 3) * ASTRIDE;
        const uint32_t boff = (uint32_t)(it & 3) * BSTRIDE;
        {
            uint32_t af0[4], af1[4];
            ldsm4(af0[0], af0[1], af0[2], af0[3], sA0 + aoff);
            ldsm4(af1[0], af1[1], af1[2], af1[3], sA0 + aoff + 16 * 48);
            uint32_t bf[NT][2];
#pragma unroll
            for (int p = 0; p < NPAIR; p++)
                ldsm4(bf[2 * p][0], bf[2 * p][1], bf[2 * p + 1][0], bf[2 * p + 1][1],
                      sB[p] + boff);
            if (TAIL)
                ldsm2(bf[NT - 1][0], bf[NT - 1][1], sB[NPAIR] + boff);
#pragma unroll
            for (int j = 0; j < NT; j++) {
                mma16(acc[0][j], af0, bf[j]);
                mma16(acc[1][j], af1, bf[j]);
            }
        }
        // Single barrier per k-step: ISSUE targets buffer (it+3)&3 == (it-1)&3,
        // which every warp finished reading before passing the barrier above.
        if (it + 3 < kiter) ISSUE((it + 3) & 3, (it + 3) * 16);
        else asm volatile("cp.async.commit_group;");
    }
#undef ISSUE

    // ---- epilogue: base cols -> fp16, comb cols -> fp32 + bias ----
#pragma unroll
    for (int i = 0; i < 2; i++) {
        int r0 = bm + rm0 + i * 16 + g;
#pragma unroll
        for (int j = 0; j < NT; j++) {
            int col = bn + cn0 + j * 8 + 2 * t4;
            if (col >= Ntot) continue;
            if (col < NBF) {
                if (r0 < M) {
                    __half2 h = __floats2half2_rn(acc[i][j][0], acc[i][j][1]);
                    *reinterpret_cast<__half2*>(&Ch[(size_t)r0 * NBF + col]) = h;
                }
                if (r0 + 8 < M) {
                    __half2 h = __floats2half2_rn(acc[i][j][2], acc[i][j][3]);
                    *reinterpret_cast<__half2*>(&Ch[(size_t)(r0 + 8) * NBF + col]) = h;
                }
            } else {
                int cc = col - NBF;
                float b0 = bc[cc], b1 = bc[cc + 1];
                if (r0 < M) {
                    float2 v = make_float2(acc[i][j][0] + b0, acc[i][j][1] + b1);
                    *reinterpret_cast<float2*>(&Cc[(size_t)r0 * 96 + cc]) = v;
                }
                if (r0 + 8 < M) {
                    float2 v = make_float2(acc[i][j][2] + b0, acc[i][j][3] + b1);
                    *reinterpret_cast<float2*>(&Cc[(size_t)(r0 + 8) * 96 + cc]) = v;
                }
            }
        }
    }
}

// ---------------- fused aggregation + combine + bias (+relu / +log_softmax) --
__device__ __forceinline__ float4 h4f(uint2 u) {
    __half2 a = *reinterpret_cast<__half2*>(&u.x);
    __half2 b = *reinterpret_cast<__half2*>(&u.y);
    float2 fa = __half22float2(a), fb = __half22float2(b);
    return make_float4(fa.x, fa.y, fb.x, fb.y);
}

template<int NBF, int F, bool RELU, bool LSM>
__global__ __launch_bounds__(256)
void k_agg(const __half* __restrict__ linh, const float* __restrict__ linc,
           const float* __restrict__ bias, void* __restrict__ out_v, int n)
{
    constexpr int HF  = 8 * F;
    constexpr int NI  = HF / 32;
    constexpr int NH4 = NBF / 4;
    constexpr int C4  = (NH4 + 31) / 32;
    __shared__ float agg_s[8][3 * NBF];
    __shared__ float comb_s[8][96];

    int gw   = (blockIdx.x * 256 + threadIdx.x) >> 5;
    int lane = threadIdx.x & 31;
    int lw   = threadIdx.x >> 5;
    if (gw >= n) return;

    int s = g_off[gw], e = g_off[gw + 1];
    int deg = e - s;

    float4 vsym[C4], vsum[C4], vmax[C4];
#pragma unroll
    for (int q = 0; q < C4; q++) {
        vsym[q] = make_float4(0.f, 0.f, 0.f, 0.f);
        vsum[q] = make_float4(0.f, 0.f, 0.f, 0.f);
        vmax[q] = make_float4(-INFINITY, -INFINITY, -INFINITY, -INFINITY);
    }

    int t = s;
    for (; t + 4 <= e; t += 4) {
        int c0 = g_adj[t], c1 = g_adj[t + 1], c2 = g_adj[t + 2], c3 = g_adj[t + 3];
        float d0 = g_adjd[t],     d1 = g_adjd[t + 1];
        float d2 = g_adjd[t + 2], d3 = g_adjd[t + 3];
        const uint2* s0 = reinterpret_cast<const uint2*>(linh + (size_t)c0 * NBF);
        const uint2* s1 = reinterpret_cast<const uint2*>(linh + (size_t)c1 * NBF);
        const uint2* s2 = reinterpret_cast<const uint2*>(linh + (size_t)c2 * NBF);
        const uint2* s3 = reinterpret_cast<const uint2*>(linh + (size_t)c3 * NBF);
#pragma unroll
        for (int q = 0; q < C4; q++) {
            int i4 = lane + q * 32;
            if (C4 > 1 && i4 >= NH4) break;
            float4 v0 = h4f(s0[i4]), v1 = h4f(s1[i4]);
            float4 v2 = h4f(s2[i4]), v3 = h4f(s3[i4]);
            vsym[q].x += (d0 * v0.x + d1 * v1.x) + (d2 * v2.x + d3 * v3.x);
            vsym[q].y += (d0 * v0.y + d1 * v1.y) + (d2 * v2.y + d3 * v3.y);
            vsym[q].z += (d0 * v0.z + d1 * v1.z) + (d2 * v2.z + d3 * v3.z);
            vsym[q].w += (d0 * v0.w + d1 * v1.w) + (d2 * v2.w + d3 * v3.w);
            vsum[q].x += (v0.x + v1.x) + (v2.x + v3.x);
            vsum[q].y += (v0.y + v1.y) + (v2.y + v3.y);
            vsum[q].z += (v0.z + v1.z) + (v2.z + v3.z);
            vsum[q].w += (v0.w + v1.w) + (v2.w + v3.w);
            vmax[q].x = fmaxf(vmax[q].x, fmaxf(fmaxf(v0.x, v1.x), fmaxf(v2.x, v3.x)));
            vmax[q].y = fmaxf(vmax[q].y, fmaxf(fmaxf(v0.y, v1.y), fmaxf(v2.y, v3.y)));
            vmax[q].z = fmaxf(vmax[q].z, fmaxf(fmaxf(v0.z, v1.z), fmaxf(v2.z, v3.z)));
            vmax[q].w = fmaxf(vmax[q].w, fmaxf(fmaxf(v0.w, v1.w), fmaxf(v2.w, v3.w)));
        }
    }
    for (; t < e; t++) {
        int c0 = g_adj[t];
        float d0 = g_adjd[t];
        const uint2* s0 = reinterpret_cast<const uint2*>(linh + (size_t)c0 * NBF);
#pragma unroll
        for (int q = 0; q < C4; q++) {
            int i4 = lane + q * 32;
            if (C4 > 1 && i4 >= NH4) break;
            float4 v0 = h4f(s0[i4]);
            vsym[q].x += d0 * v0.x; vsym[q].y += d0 * v0.y;
            vsym[q].z += d0 * v0.z; vsym[q].w += d0 * v0.w;
            vsum[q].x += v0.x; vsum[q].y += v0.y;
            vsum[q].z += v0.z; vsum[q].w += v0.w;
            vmax[q].x = fmaxf(vmax[q].x, v0.x); vmax[q].y = fmaxf(vmax[q].y, v0.y);
            vmax[q].z = fmaxf(vmax[q].z, v0.z); vmax[q].w = fmaxf(vmax[q].w, v0.w);
        }
    }

    float dn   = g_dinv[gw];
    float invd = (deg > 0) ? (1.0f / (float)deg) : 0.0f;

    float4* arow0 = reinterpret_cast<float4*>(&agg_s[lw][0]);
    float4* arow1 = reinterpret_cast<float4*>(&agg_s[lw][NBF]);
    float4* arow2 = reinterpret_cast<float4*>(&agg_s[lw][2 * NBF]);
#pragma unroll
    for (int q = 0; q < C4; q++) {
        int i4 = lane + q * 32;
        if (C4 > 1 && i4 >= NH4) break;
        float4 sy = vsym[q];
        sy.x *= dn; sy.y *= dn; sy.z *= dn; sy.w *= dn;
        float4 me = vsum[q];
        me.x *= invd; me.y *= invd; me.z *= invd; me.w *= invd;
        float4 mx = vmax[q];
        if (deg == 0) mx = make_float4(0.f, 0.f, 0.f, 0.f);
        arow0[i4] = sy;
        arow1[i4] = me;
        arow2[i4] = mx;
    }

    const float* comb = linc + (size_t)gw * 96;
    comb_s[lw][lane]      = comb[lane];
    comb_s[lw][lane + 32] = comb[lane + 32];
    comb_s[lw][lane + 64] = comb[lane + 64];
    __syncwarp();

    float vals[NI];
#pragma unroll
    for (int i = 0; i < NI; i++) {
        int c = lane + i * 32;
        int h = c / F, f = c % F;
        float v = bias[c];
        const float* cb = &comb_s[lw][h * 12];
        const float* ag = &agg_s[lw][0];
#pragma unroll
        for (int k = 0; k < 12; k++) v = fmaf(cb[k], ag[k * F + f], v);
        if (RELU) v = fmaxf(v, 0.0f);
        vals[i] = v;
    }

    if (!LSM) {
        __half* out = (__half*)out_v;
#pragma unroll
        for (int i = 0; i < NI; i++)
            out[(size_t)gw * HF + lane + i * 32] = __float2half_rn(vals[i]);
    } else {
        float* out = (float*)out_v;
        float m = -INFINITY;
#pragma unroll
        for (int i = 0; i < NI; i++) {
            int c = lane + i * 32;
            m = fmaxf(m, (c < OUTT) ? vals[i] : -INFINITY);
        }
#pragma unroll
        for (int o = 16; o; o >>= 1) m = fmaxf(m, __shfl_xor_sync(0xffffffffu, m, o));
        float sum = 0.0f;
#pragma unroll
        for (int i = 0; i < NI; i++) {
            int c = lane + i * 32;
            if (c < OUTT) sum += expf(vals[i] - m);
        }
#pragma unroll
        for (int o = 16; o; o >>= 1) sum += __shfl_xor_sync(0xffffffffu, sum, o);
        float l = m + logf(sum);
#pragma unroll
        for (int i = 0; i < NI; i++) {
            int c = lane + i * 32;
            if (c < OUTT) out[(size_t)gw * OUTT + c] = vals[i] - l;
        }
    }
}

// ---------------- launch --------------------------------------------------------
extern "C" void kernel_launch(void* const* d_in, const int* in_sizes, int n_in,
                              void* d_out, int out_size)
{
    const float* x   = (const float*)d_in[0];
    const int*   ei  = (const int*)d_in[1];
    int N = in_sizes[0] / 128;
    int E = in_sizes[1] / 2;
    if (N > NMAX) N = NMAX;
    if (E > EMAX) E = EMAX;
    const int* row = ei;
    const int* col = ei + E;

    const float* Wb0 = (const float*)d_in[2];
    const float* Wc0 = (const float*)d_in[3];
    const float* bc0 = (const float*)d_in[4];
    const float* b0  = (const float*)d_in[5];
    const float* Wb1 = (const float*)d_in[6];
    const float* Wc1 = (const float*)d_in[7];
    const float* bc1 = (const float*)d_in[8];
    const float* b1  = (const float*)d_in[9];
    const float* Wb2 = (const float*)d_in[10];
    const float* Wc2 = (const float*)d_in[11];
    const float* bc2 = (const float*)d_in[12];
    const float* b2  = (const float*)d_in[13];

    __half* linh; float* linc; __half* xh; __half* hA; __half* hB;
    __half* wt0; __half* wt1; __half* wt2;
    cudaGetSymbolAddress((void**)&linh, g_linh);
    cudaGetSymbolAddress((void**)&linc, g_linc);
    cudaGetSymbolAddress((void**)&xh,   g_xh);
    cudaGetSymbolAddress((void**)&hA,   g_hA);
    cudaGetSymbolAddress((void**)&hB,   g_hB);
    cudaGetSymbolAddress((void**)&wt0,  g_wt0);
    cudaGetSymbolAddress((void**)&wt1,  g_wt1);
    cudaGetSymbolAddress((void**)&wt2,  g_wt2);

    const int T  = 256;
    const int gy = (N + 127) / 128;
    const int ab = (N + 7) / 8;
    const int sb = (N + 255) / 256;
    const int n4 = N * 128 / 4;
    const int WALL = 224 * 128 + 224 * 256 + 288 * 256;

    // Fork: CSR chain on a side stream, converts+GEMM0 on the main stream.
    cudaStream_t s1;
    cudaStreamCreateWithFlags(&s1, cudaStreamNonBlocking);
    cudaEvent_t evRoot, evCsr;
    cudaEventCreateWithFlags(&evRoot, cudaEventDisableTiming);
    cudaEventCreateWithFlags(&evCsr,  cudaEventDisableTiming);

    cudaEventRecord(evRoot, 0);
    cudaStreamWaitEvent(s1, evRoot, 0);

    // side stream: CSR build
    k_zero   <<<(N + T - 1) / T, T, 0, s1>>>(N);
    k_deg    <<<(E + T - 1) / T, T, 0, s1>>>(row, E);
    k_scan1  <<<sb, 256, 0, s1>>>(N);
    k_scan2  <<<1, 256, 0, s1>>>(sb);
    k_scan3  <<<sb, 256, 0, s1>>>(N, E);
    k_scatter<<<(E + T - 1) / T, T, 0, s1>>>(row, col, E);
    cudaEventRecord(evCsr, s1);

    // main stream: converts + layer-0 GEMM (independent of CSR)
    k_cvt_x   <<<(n4 + T - 1) / T, T>>>(x, (__half2*)xh, n4);
    k_cvt_wall<<<(WALL + T - 1) / T, T>>>(Wb0, Wc0, Wb1, Wc1, Wb2, Wc2, wt0, wt1, wt2);
    k_gemm_h<7><<<dim3(2, gy), 256>>>(xh, wt0, bc0, linh, linc, N, 128, 128, 224);

    // join
    cudaStreamWaitEvent(0, evCsr, 0);

    k_agg<128, 32, true, false><<<ab, 256>>>(linh, linc, b0, hA, N);

    k_gemm_h<7><<<dim3(2, gy), 256>>>(hA, wt1, bc1, linh, linc, N, 256, 128, 224);
    k_agg<128, 32, true, false><<<ab, 256>>>(linh, linc, b1, hB, N);

    k_gemm_h<6><<<dim3(3, gy), 256>>>(hB, wt2, bc2, linh, linc, N, 256, 176, 272);
    k_agg<176, 44, false, true><<<ab, 256>>>(linh, linc, b2, d_out, N);
}

// round 11
// speedup vs baseline: 1.4332x; 1.0218x over previous
#include <cuda_runtime.h>
#include <cuda_fp16.h>
#include <math.h>
#include <stdint.h>

#define NMAX   50000
#define EMAX   600000
#define OUTT   349

// ---------------- scratch (device globals) ----------------------------------
__device__ int    g_deg[NMAX];
__device__ float  g_dinv[NMAX];
__device__ int    g_off[NMAX];
__device__ int    g_cur[NMAX];
__device__ int    g_adj[EMAX];
__device__ float  g_adjd[EMAX];
__device__ int    g_total;
__device__ __half g_linh[(size_t)NMAX * 176];   // bases (fp16), pitch = NBF
__device__ float  g_linc[(size_t)NMAX * 96];    // comb (fp32), pitch = 96
__device__ __half g_xh[(size_t)NMAX * 128];
__device__ __half g_hA[(size_t)NMAX * 256];
__device__ __half g_hB[(size_t)NMAX * 256];
__device__ __half g_wt0[224 * 128];
__device__ __half g_wt1[224 * 256];
__device__ __half g_wt2[288 * 256];

// ---------------- converts ----------------------------------------------------
__global__ void k_cvt_x(const float* __restrict__ x, __half2* __restrict__ xh, int n4) {
    int i = blockIdx.x * blockDim.x + threadIdx.x;
    if (i < n4) {
        float4 v = reinterpret_cast<const float4*>(x)[i];
        xh[2 * i]     = __floats2half2_rn(v.x, v.y);
        xh[2 * i + 1] = __floats2half2_rn(v.z, v.w);
    }
}

__device__ __forceinline__ void cvt_one(const float* Wb, const float* Wc, __half* Wt,
                                        int idx, int K, int NBF, int Ntot) {
    int n = idx / K, k = idx % K;
    float v = 0.0f;
    if (n < NBF)       v = Wb[k * NBF + n];
    else if (n < Ntot) v = Wc[k * (Ntot - NBF) + (n - NBF)];
    Wt[idx] = __float2half_rn(v);
}

__global__ void k_cvt_w0(const float* __restrict__ Wb0, const float* __restrict__ Wc0,
                         __half* __restrict__ wt0) {
    int idx = blockIdx.x * blockDim.x + threadIdx.x;
    if (idx < 224 * 128) cvt_one(Wb0, Wc0, wt0, idx, 128, 128, 224);
}

__global__ void k_cvt_w12(const float* __restrict__ Wb1, const float* __restrict__ Wc1,
                          const float* __restrict__ Wb2, const float* __restrict__ Wc2,
                          __half* __restrict__ wt1, __half* __restrict__ wt2) {
    const int S1 = 224 * 256, S2 = 288 * 256;
    int idx = blockIdx.x * blockDim.x + threadIdx.x;
    if (idx < S1)           cvt_one(Wb1, Wc1, wt1, idx,      256, 128, 224);
    else if (idx < S1 + S2) cvt_one(Wb2, Wc2, wt2, idx - S1, 256, 176, 272);
}

// ---------------- CSR build --------------------------------------------------
__global__ void k_zero(int n) {
    int i = blockIdx.x * blockDim.x + threadIdx.x;
    if (i < n) g_deg[i] = 0;
    if (blockIdx.x == 0 && threadIdx.x == 0) g_total = 0;
}

__global__ void k_deg(const int* __restrict__ row, int e) {
    int i = blockIdx.x * blockDim.x + threadIdx.x;
    if (i < e) atomicAdd(&g_deg[row[i]], 1);
}

// offsets via warp-aggregated atomic allocation (order across warps arbitrary;
// adjacency rows stay contiguous, float-sum order tolerance absorbs the rest)
__global__ void k_off(int n) {
    int i = blockIdx.x * blockDim.x + threadIdx.x;
    int lane = threadIdx.x & 31;
    int d = (i < n) ? g_deg[i] : 0;
    int s = d;
#pragma unroll
    for (int o = 1; o < 32; o <<= 1) {
        int u = __shfl_up_sync(0xffffffffu, s, o);
        if (lane >= o) s += u;
    }
    int total = __shfl_sync(0xffffffffu, s, 31);
    int base = 0;
    if (lane == 0) base = atomicAdd(&g_total, total);
    base = __shfl_sync(0xffffffffu, base, 0);
    if (i < n) {
        int off = base + s - d;
        g_off[i] = off;
        g_cur[i] = off;
        g_dinv[i] = (d > 0) ? rsqrtf((float)d) : 0.0f;
    }
}

__global__ void k_scatter(const int* __restrict__ row, const int* __restrict__ col, int e) {
    int i = blockIdx.x * blockDim.x + threadIdx.x;
    if (i < e) {
        int r = row[i];
        int c = col[i];
        int p = atomicAdd(&g_cur[r], 1);
        g_adj[p]  = c;
        g_adjd[p] = g_dinv[c];
    }
}

// ---------------- fp16 tensor-core GEMM, cp.async + ldmatrix ------------------
__device__ __forceinline__ void mma16(float* c, const uint32_t* a, const uint32_t* b) {
    asm volatile(
        "mma.sync.aligned.m16n8k16.row.col.f32.f16.f16.f32 "
        "{%0,%1,%2,%3}, {%4,%5,%6,%7}, {%8,%9}, {%0,%1,%2,%3};"
        : "+f"(c[0]), "+f"(c[1]), "+f"(c[2]), "+f"(c[3])
        : "r"(a[0]), "r"(a[1]), "r"(a[2]), "r"(a[3]), "r"(b[0]), "r"(b[1]));
}

__device__ __forceinline__ void cpa16(uint32_t saddr, const void* gptr, bool pred) {
    int sz = pred ? 16 : 0;
    asm volatile("cp.async.ca.shared.global [%0], [%1], 16, %2;"
                 :: "r"(saddr), "l"(gptr), "r"(sz));
}

__device__ __forceinline__ void ldsm4(uint32_t& a, uint32_t& b, uint32_t& c, uint32_t& d,
                                      uint32_t addr) {
    asm volatile("ldmatrix.sync.aligned.m8n8.x4.shared.b16 {%0,%1,%2,%3}, [%4];"
                 : "=r"(a), "=r"(b), "=r"(c), "=r"(d) : "r"(addr));
}
__device__ __forceinline__ void ldsm2(uint32_t& a, uint32_t& b, uint32_t addr) {
    asm volatile("ldmatrix.sync.aligned.m8n8.x2.shared.b16 {%0,%1}, [%2];"
                 : "=r"(a), "=r"(b) : "r"(addr));
}

template<int NT>
__global__ __launch_bounds__(256)
void k_gemm_h(const __half* __restrict__ A, const __half* __restrict__ Wt,
              const float* __restrict__ bc,
              __half* __restrict__ Ch, float* __restrict__ Cc,
              int M, int K, int NBF, int Ntot)
{
    constexpr int BN    = 16 * NT;
    constexpr int NPAIR = NT / 2;
    constexpr int TAIL  = NT & 1;
    __shared__ __align__(16) uint32_t As[4][128][12];
    __shared__ __align__(16) uint32_t Bs[4][BN][12];

    const int tid  = threadIdx.x;
    const int bm   = blockIdx.y * 128;
    const int bn   = blockIdx.x * BN;
    const int w    = tid >> 5, lane = tid & 31;
    const int wm   = w & 3,   wn   = w >> 2;
    const int g    = lane >> 2, t4 = lane & 3;

    const int crow = tid >> 1, ch = tid & 1;
    const bool aval = (bm + crow) < M;
    const __half* agp = A  + (size_t)(bm + crow) * K + ch * 8;
    const __half* bgp = Wt + (size_t)(bn + crow) * K + ch * 8;
    const bool bv = (tid < 2 * BN);

    uint32_t a_s = (uint32_t)__cvta_generic_to_shared(&As[0][crow][ch * 4]);
    uint32_t b_s = (uint32_t)__cvta_generic_to_shared(&Bs[0][crow][ch * 4]);
    constexpr uint32_t ASTRIDE = 128 * 12 * 4;
    constexpr uint32_t BSTRIDE = BN * 12 * 4;

    const int rm0 = wm * 32;
    const int cn0 = wn * NT * 8;

    const int arow = rm0 + ((lane >> 3) & 1) * 8 + (lane & 7);
    const int awrd = (lane >> 4) * 4;
    const uint32_t sA0 = (uint32_t)__cvta_generic_to_shared(&As[0][arow][awrd]);
    uint32_t sB[NPAIR + TAIL];
#pragma unroll
    for (int p = 0; p < NPAIR; p++) {
        int brow = cn0 + p * 16 + ((lane >> 4) & 1) * 8 + (lane & 7);
        int bwrd = ((lane >> 3) & 1) * 4;
        sB[p] = (uint32_t)__cvta_generic_to_shared(&Bs[0][brow][bwrd]);
    }
    if (TAIL) {
        int brow = cn0 + NPAIR * 16 + (lane & 7);
        int bwrd = ((lane >> 3) & 1) * 4;
        sB[NPAIR] = (uint32_t)__cvta_generic_to_shared(&Bs[0][brow][bwrd]);
    }

#define ISSUE(S, K0)                                                   \
    do {                                                               \
        cpa16(a_s + (S) * ASTRIDE, agp + (K0), aval);                  \
        if (bv) cpa16(b_s + (S) * BSTRIDE, bgp + (K0), true);          \
        asm volatile("cp.async.commit_group;");                        \
    } while (0)

    float acc[2][NT][4];
#pragma unroll
    for (int i = 0; i < 2; i++)
#pragma unroll
        for (int j = 0; j < NT; j++)
#pragma unroll
            for (int r = 0; r < 4; r++) acc[i][j][r] = 0.0f;

    const int kiter = K >> 4;
    ISSUE(0, 0);
    ISSUE(1, 16);
    ISSUE(2, 32);

    for (int it = 0; it < kiter; it++) {
        asm volatile("cp.async.wait_group 2;");
        __syncthreads();
        const uint32_t aoff = (uint32_t)(it & 3) * ASTRIDE;
        const uint32_t boff = (uint32_t)(it & 3) * BSTRIDE;
        {
            uint32_t af0[4], af1[4];
            ldsm4(af0[0], af0[1], af0[2], af0[3], sA0 + aoff);
            ldsm4(af1[0], af1[1], af1[2], af1[3], sA0 + aoff + 16 * 48);
            uint32_t bf[NT][2];
#pragma unroll
            for (int p = 0; p < NPAIR; p++)
                ldsm4(bf[2 * p][0], bf[2 * p][1], bf[2 * p + 1][0], bf[2 * p + 1][1],
                      sB[p] + boff);
            if (TAIL)
                ldsm2(bf[NT - 1][0], bf[NT - 1][1], sB[NPAIR] + boff);
#pragma unroll
            for (int j = 0; j < NT; j++) {
                mma16(acc[0][j], af0, bf[j]);
                mma16(acc[1][j], af1, bf[j]);
            }
        }
        if (it + 3 < kiter) ISSUE((it + 3) & 3, (it + 3) * 16);
        else asm volatile("cp.async.commit_group;");
    }
#undef ISSUE

    // ---- epilogue ----
#pragma unroll
    for (int i = 0; i < 2; i++) {
        int r0 = bm + rm0 + i * 16 + g;
#pragma unroll
        for (int j = 0; j < NT; j++) {
            int col = bn + cn0 + j * 8 + 2 * t4;
            if (col >= Ntot) continue;
            if (col < NBF) {
                if (r0 < M) {
                    __half2 h = __floats2half2_rn(acc[i][j][0], acc[i][j][1]);
                    *reinterpret_cast<__half2*>(&Ch[(size_t)r0 * NBF + col]) = h;
                }
                if (r0 + 8 < M) {
                    __half2 h = __floats2half2_rn(acc[i][j][2], acc[i][j][3]);
                    *reinterpret_cast<__half2*>(&Ch[(size_t)(r0 + 8) * NBF + col]) = h;
                }
            } else {
                int cc = col - NBF;
                float b0 = bc[cc], b1 = bc[cc + 1];
                if (r0 < M) {
                    float2 v = make_float2(acc[i][j][0] + b0, acc[i][j][1] + b1);
                    *reinterpret_cast<float2*>(&Cc[(size_t)r0 * 96 + cc]) = v;
                }
                if (r0 + 8 < M) {
                    float2 v = make_float2(acc[i][j][2] + b0, acc[i][j][3] + b1);
                    *reinterpret_cast<float2*>(&Cc[(size_t)(r0 + 8) * 96 + cc]) = v;
                }
            }
        }
    }
}

// ---------------- fused aggregation + combine + bias (+relu / +log_softmax) --
__device__ __forceinline__ float4 h4f(uint2 u) {
    __half2 a = *reinterpret_cast<__half2*>(&u.x);
    __half2 b = *reinterpret_cast<__half2*>(&u.y);
    float2 fa = __half22float2(a), fb = __half22float2(b);
    return make_float4(fa.x, fa.y, fb.x, fb.y);
}

template<int NBF, int F, bool RELU, bool LSM>
__global__ __launch_bounds__(256)
void k_agg(const __half* __restrict__ linh, const float* __restrict__ linc,
           const float* __restrict__ bias, void* __restrict__ out_v, int n)
{
    constexpr int HF  = 8 * F;
    constexpr int NI  = HF / 32;
    constexpr int NH4 = NBF / 4;
    constexpr int C4  = (NH4 + 31) / 32;
    constexpr int UN  = (C4 == 1) ? 8 : 4;
    __shared__ float agg_s[8][3 * NBF];
    __shared__ float comb_s[8][96];

    int gw   = (blockIdx.x * 256 + threadIdx.x) >> 5;
    int lane = threadIdx.x & 31;
    int lw   = threadIdx.x >> 5;
    if (gw >= n) return;

    int s = g_off[gw];
    int deg = g_deg[gw];
    int e = s + deg;

    float4 vsym[C4], vsum[C4], vmax[C4];
#pragma unroll
    for (int q = 0; q < C4; q++) {
        vsym[q] = make_float4(0.f, 0.f, 0.f, 0.f);
        vsum[q] = make_float4(0.f, 0.f, 0.f, 0.f);
        vmax[q] = make_float4(-INFINITY, -INFINITY, -INFINITY, -INFINITY);
    }

    int t = s;
    for (; t + UN <= e; t += UN) {
        int cc[UN]; float dd[UN]; const uint2* sp[UN];
#pragma unroll
        for (int u = 0; u < UN; u++) {
            cc[u] = g_adj[t + u];
            dd[u] = g_adjd[t + u];
            sp[u] = reinterpret_cast<const uint2*>(linh + (size_t)cc[u] * NBF);
        }
#pragma unroll
        for (int q = 0; q < C4; q++) {
            int i4 = lane + q * 32;
            if (C4 > 1 && i4 >= NH4) break;
            float4 vv[UN];
#pragma unroll
            for (int u = 0; u < UN; u++) vv[u] = h4f(sp[u][i4]);
#pragma unroll
            for (int u = 0; u < UN; u++) {
                vsym[q].x += dd[u] * vv[u].x; vsym[q].y += dd[u] * vv[u].y;
                vsym[q].z += dd[u] * vv[u].z; vsym[q].w += dd[u] * vv[u].w;
                vsum[q].x += vv[u].x; vsum[q].y += vv[u].y;
                vsum[q].z += vv[u].z; vsum[q].w += vv[u].w;
                vmax[q].x = fmaxf(vmax[q].x, vv[u].x);
                vmax[q].y = fmaxf(vmax[q].y, vv[u].y);
                vmax[q].z = fmaxf(vmax[q].z, vv[u].z);
                vmax[q].w = fmaxf(vmax[q].w, vv[u].w);
            }
        }
    }
    for (; t < e; t++) {
        int c0 = g_adj[t];
        float d0 = g_adjd[t];
        const uint2* s0 = reinterpret_cast<const uint2*>(linh + (size_t)c0 * NBF);
#pragma unroll
        for (int q = 0; q < C4; q++) {
            int i4 = lane + q * 32;
            if (C4 > 1 && i4 >= NH4) break;
            float4 v0 = h4f(s0[i4]);
            vsym[q].x += d0 * v0.x; vsym[q].y += d0 * v0.y;
            vsym[q].z += d0 * v0.z; vsym[q].w += d0 * v0.w;
            vsum[q].x += v0.x; vsum[q].y += v0.y;
            vsum[q].z += v0.z; vsum[q].w += v0.w;
            vmax[q].x = fmaxf(vmax[q].x, v0.x); vmax[q].y = fmaxf(vmax[q].y, v0.y);
            vmax[q].z = fmaxf(vmax[q].z, v0.z); vmax[q].w = fmaxf(vmax[q].w, v0.w);
        }
    }

    float dn   = g_dinv[gw];
    float invd = (deg > 0) ? (1.0f / (float)deg) : 0.0f;

    float4* arow0 = reinterpret_cast<float4*>(&agg_s[lw][0]);
    float4* arow1 = reinterpret_cast<float4*>(&agg_s[lw][NBF]);
    float4* arow2 = reinterpret_cast<float4*>(&agg_s[lw][2 * NBF]);
#pragma unroll
    for (int q = 0; q < C4; q++) {
        int i4 = lane + q * 32;
        if (C4 > 1 && i4 >= NH4) break;
        float4 sy = vsym[q];
        sy.x *= dn; sy.y *= dn; sy.z *= dn; sy.w *= dn;
        float4 me = vsum[q];
        me.x *= invd; me.y *= invd; me.z *= invd; me.w *= invd;
        float4 mx = vmax[q];
        if (deg == 0) mx = make_float4(0.f, 0.f, 0.f, 0.f);
        arow0[i4] = sy;
        arow1[i4] = me;
        arow2[i4] = mx;
    }

    const float* comb = linc + (size_t)gw * 96;
    comb_s[lw][lane]      = comb[lane];
    comb_s[lw][lane + 32] = comb[lane + 32];
    comb_s[lw][lane + 64] = comb[lane + 64];
    __syncwarp();

    float vals[NI];
#pragma unroll
    for (int i = 0; i < NI; i++) {
        int c = lane + i * 32;
        int h = c / F, f = c % F;
        float v = bias[c];
        const float* cb = &comb_s[lw][h * 12];
        const float* ag = &agg_s[lw][0];
#pragma unroll
        for (int k = 0; k < 12; k++) v = fmaf(cb[k], ag[k * F + f], v);
        if (RELU) v = fmaxf(v, 0.0f);
        vals[i] = v;
    }

    if (!LSM) {
        __half* out = (__half*)out_v;
#pragma unroll
        for (int i = 0; i < NI; i++)
            out[(size_t)gw * HF + lane + i * 32] = __float2half_rn(vals[i]);
    } else {
        float* out = (float*)out_v;
        float m = -INFINITY;
#pragma unroll
        for (int i = 0; i < NI; i++) {
            int c = lane + i * 32;
            m = fmaxf(m, (c < OUTT) ? vals[i] : -INFINITY);
        }
#pragma unroll
        for (int o = 16; o; o >>= 1) m = fmaxf(m, __shfl_xor_sync(0xffffffffu, m, o));
        float sum = 0.0f;
#pragma unroll
        for (int i = 0; i < NI; i++) {
            int c = lane + i * 32;
            if (c < OUTT) sum += expf(vals[i] - m);
        }
#pragma unroll
        for (int o = 16; o; o >>= 1) sum += __shfl_xor_sync(0xffffffffu, sum, o);
        float l = m + logf(sum);
#pragma unroll
        for (int i = 0; i < NI; i++) {
            int c = lane + i * 32;
            if (c < OUTT) out[(size_t)gw * OUTT + c] = vals[i] - l;
        }
    }
}

// ---------------- launch --------------------------------------------------------
extern "C" void kernel_launch(void* const* d_in, const int* in_sizes, int n_in,
                              void* d_out, int out_size)
{
    const float* x   = (const float*)d_in[0];
    const int*   ei  = (const int*)d_in[1];
    int N = in_sizes[0] / 128;
    int E = in_sizes[1] / 2;
    if (N > NMAX) N = NMAX;
    if (E > EMAX) E = EMAX;
    const int* row = ei;
    const int* col = ei + E;

    const float* Wb0 = (const float*)d_in[2];
    const float* Wc0 = (const float*)d_in[3];
    const float* bc0 = (const float*)d_in[4];
    const float* b0  = (const float*)d_in[5];
    const float* Wb1 = (const float*)d_in[6];
    const float* Wc1 = (const float*)d_in[7];
    const float* bc1 = (const float*)d_in[8];
    const float* b1  = (const float*)d_in[9];
    const float* Wb2 = (const float*)d_in[10];
    const float* Wc2 = (const float*)d_in[11];
    const float* bc2 = (const float*)d_in[12];
    const float* b2  = (const float*)d_in[13];

    __half* linh; float* linc; __half* xh; __half* hA; __half* hB;
    __half* wt0; __half* wt1; __half* wt2;
    cudaGetSymbolAddress((void**)&linh, g_linh);
    cudaGetSymbolAddress((void**)&linc, g_linc);
    cudaGetSymbolAddress((void**)&xh,   g_xh);
    cudaGetSymbolAddress((void**)&hA,   g_hA);
    cudaGetSymbolAddress((void**)&hB,   g_hB);
    cudaGetSymbolAddress((void**)&wt0,  g_wt0);
    cudaGetSymbolAddress((void**)&wt1,  g_wt1);
    cudaGetSymbolAddress((void**)&wt2,  g_wt2);

    const int T  = 256;
    const int gy = (N + 127) / 128;
    const int ab = (N + 7) / 8;
    const int n4 = N * 128 / 4;
    const int W12 = 224 * 256 + 288 * 256;

    // Streams/events created ONCE on the first (uncaptured) correctness call
    // and reused on every later call — no per-call driver allocations, so the
    // graph-teardown memory baseline is undisturbed. Deterministic: the same
    // launch DAG is recorded on every call.
    static cudaStream_t s1 = nullptr, s2 = nullptr;
    static cudaEvent_t evRoot = nullptr, evCsr = nullptr, evW12 = nullptr;
    if (!s1) {
        cudaStreamCreateWithFlags(&s1, cudaStreamNonBlocking);
        cudaStreamCreateWithFlags(&s2, cudaStreamNonBlocking);
        cudaEventCreateWithFlags(&evRoot, cudaEventDisableTiming);
        cudaEventCreateWithFlags(&evCsr,  cudaEventDisableTiming);
        cudaEventCreateWithFlags(&evW12,  cudaEventDisableTiming);
    }

    cudaEventRecord(evRoot, 0);
    cudaStreamWaitEvent(s1, evRoot, 0);
    cudaStreamWaitEvent(s2, evRoot, 0);

    // s1: CSR build (4 kernels; warp-aggregated offset allocation, no scans)
    k_zero   <<<(N + T - 1) / T, T, 0, s1>>>(N);
    k_deg    <<<(E + T - 1) / T, T, 0, s1>>>(row, E);
    k_off    <<<(N + T - 1) / T, T, 0, s1>>>(N);
    k_scatter<<<(E + T - 1) / T, T, 0, s1>>>(row, col, E);
    cudaEventRecord(evCsr, s1);

    // s2: layer-1/2 weight converts (needed only at gemm1)
    k_cvt_w12<<<(W12 + T - 1) / T, T, 0, s2>>>(Wb1, Wc1, Wb2, Wc2, wt1, wt2);
    cudaEventRecord(evW12, s2);

    // main: x convert + layer-0 weights + layer-0 GEMM
    k_cvt_x  <<<(n4 + T - 1) / T, T>>>(x, (__half2*)xh, n4);
    k_cvt_w0 <<<(224 * 128 + T - 1) / T, T>>>(Wb0, Wc0, wt0);
    k_gemm_h<7><<<dim3(2, gy), 256>>>(xh, wt0, bc0, linh, linc, N, 128, 128, 224);

    // joins
    cudaStreamWaitEvent(0, evCsr, 0);
    cudaStreamWaitEvent(0, evW12, 0);

    k_agg<128, 32, true, false><<<ab, 256>>>(linh, linc, b0, hA, N);

    k_gemm_h<7><<<dim3(2, gy), 256>>>(hA, wt1, bc1, linh, linc, N, 256, 128, 224);
    k_agg<128, 32, true, false><<<ab, 256>>>(linh, linc, b1, hB, N);

    k_gemm_h<6><<<dim3(3, gy), 256>>>(hB, wt2, bc2, linh, linc, N, 256, 176, 272);
    k_agg<176, 44, false, true><<<ab, 256>>>(linh, linc, b2, d_out, N);
}

// round 12
// speedup vs baseline: 1.4645x; 1.0218x over previous
#include <cuda_runtime.h>
#include <cuda_fp16.h>
#include <math.h>
#include <stdint.h>

#define NMAX   50000
#define EMAX   600000
#define OUTT   349

// ---------------- scratch (device globals) ----------------------------------
__device__ int    g_deg[NMAX];
__device__ float  g_dinv[NMAX];
__device__ int    g_off[NMAX];
__device__ int    g_cur[NMAX];
__device__ int    g_adj[EMAX];
__device__ float  g_adjd[EMAX];
__device__ int    g_total;
__device__ __half g_linh[(size_t)NMAX * 176];   // bases (fp16), pitch = NBF
__device__ float  g_linc[(size_t)NMAX * 96];    // comb (fp32), pitch = 96
__device__ __half g_xh[(size_t)NMAX * 128];
__device__ __half g_hA[(size_t)NMAX * 256];
__device__ __half g_hB[(size_t)NMAX * 256];
__device__ __half g_wt0[224 * 128];
__device__ __half g_wt1[224 * 256];
__device__ __half g_wt2[288 * 256];

// ---------------- PDL helpers --------------------------------------------------
__device__ __forceinline__ void gdc_wait()  { asm volatile("griddepcontrol.wait;" ::: "memory"); }
__device__ __forceinline__ void gdc_launch(){ asm volatile("griddepcontrol.launch_dependents;" ::: "memory"); }

// ---------------- converts ----------------------------------------------------
__device__ __forceinline__ void cvt_one(const float* Wb, const float* Wc, __half* Wt,
                                        int idx, int K, int NBF, int Ntot) {
    int n = idx / K, k = idx % K;
    float v = 0.0f;
    if (n < NBF)       v = Wb[k * NBF + n];
    else if (n < Ntot) v = Wc[k * (Ntot - NBF) + (n - NBF)];
    Wt[idx] = __float2half_rn(v);
}

// x convert + layer-0 weight convert, one kernel
__global__ void k_cvt_xw0(const float* __restrict__ x, __half2* __restrict__ xh, int n4,
                          const float* __restrict__ Wb0, const float* __restrict__ Wc0,
                          __half* __restrict__ wt0) {
    int i = blockIdx.x * blockDim.x + threadIdx.x;
    if (i < n4) {
        float4 v = reinterpret_cast<const float4*>(x)[i];
        xh[2 * i]     = __floats2half2_rn(v.x, v.y);
        xh[2 * i + 1] = __floats2half2_rn(v.z, v.w);
    } else {
        int idx = i - n4;
        if (idx < 224 * 128) cvt_one(Wb0, Wc0, wt0, idx, 128, 128, 224);
    }
    gdc_launch();
}

__global__ void k_cvt_w12(const float* __restrict__ Wb1, const float* __restrict__ Wc1,
                          const float* __restrict__ Wb2, const float* __restrict__ Wc2,
                          __half* __restrict__ wt1, __half* __restrict__ wt2) {
    const int S1 = 224 * 256, S2 = 288 * 256;
    int idx = blockIdx.x * blockDim.x + threadIdx.x;
    if (idx < S1)           cvt_one(Wb1, Wc1, wt1, idx,      256, 128, 224);
    else if (idx < S1 + S2) cvt_one(Wb2, Wc2, wt2, idx - S1, 256, 176, 272);
}

// ---------------- CSR build --------------------------------------------------
__global__ void k_zero(int n) {
    int i = blockIdx.x * blockDim.x + threadIdx.x;
    if (i < n) g_deg[i] = 0;
    if (blockIdx.x == 0 && threadIdx.x == 0) g_total = 0;
}

__global__ void k_deg(const int* __restrict__ row, int e) {
    int i = blockIdx.x * blockDim.x + threadIdx.x;
    if (i < e) atomicAdd(&g_deg[row[i]], 1);
}

__global__ void k_off(int n) {
    int i = blockIdx.x * blockDim.x + threadIdx.x;
    int lane = threadIdx.x & 31;
    int d = (i < n) ? g_deg[i] : 0;
    int s = d;
#pragma unroll
    for (int o = 1; o < 32; o <<= 1) {
        int u = __shfl_up_sync(0xffffffffu, s, o);
        if (lane >= o) s += u;
    }
    int total = __shfl_sync(0xffffffffu, s, 31);
    int base = 0;
    if (lane == 0) base = atomicAdd(&g_total, total);
    base = __shfl_sync(0xffffffffu, base, 0);
    if (i < n) {
        int off = base + s - d;
        g_off[i] = off;
        g_cur[i] = off;
        g_dinv[i] = (d > 0) ? rsqrtf((float)d) : 0.0f;
    }
}

__global__ void k_scatter(const int* __restrict__ row, const int* __restrict__ col, int e) {
    int i = blockIdx.x * blockDim.x + threadIdx.x;
    if (i < e) {
        int r = row[i];
        int c = col[i];
        int p = atomicAdd(&g_cur[r], 1);
        g_adj[p]  = c;
        g_adjd[p] = g_dinv[c];
    }
}

// ---------------- fp16 tensor-core GEMM, cp.async + ldmatrix + PDL ------------
__device__ __forceinline__ void mma16(float* c, const uint32_t* a, const uint32_t* b) {
    asm volatile(
        "mma.sync.aligned.m16n8k16.row.col.f32.f16.f16.f32 "
        "{%0,%1,%2,%3}, {%4,%5,%6,%7}, {%8,%9}, {%0,%1,%2,%3};"
        : "+f"(c[0]), "+f"(c[1]), "+f"(c[2]), "+f"(c[3])
        : "r"(a[0]), "r"(a[1]), "r"(a[2]), "r"(a[3]), "r"(b[0]), "r"(b[1]));
}

__device__ __forceinline__ void cpa16(uint32_t saddr, const void* gptr, bool pred) {
    int sz = pred ? 16 : 0;
    asm volatile("cp.async.ca.shared.global [%0], [%1], 16, %2;"
                 :: "r"(saddr), "l"(gptr), "r"(sz));
}

__device__ __forceinline__ void ldsm4(uint32_t& a, uint32_t& b, uint32_t& c, uint32_t& d,
                                      uint32_t addr) {
    asm volatile("ldmatrix.sync.aligned.m8n8.x4.shared.b16 {%0,%1,%2,%3}, [%4];"
                 : "=r"(a), "=r"(b), "=r"(c), "=r"(d) : "r"(addr));
}
__device__ __forceinline__ void ldsm2(uint32_t& a, uint32_t& b, uint32_t addr) {
    asm volatile("ldmatrix.sync.aligned.m8n8.x2.shared.b16 {%0,%1}, [%2];"
                 : "=r"(a), "=r"(b) : "r"(addr));
}

template<int NT>
__global__ __launch_bounds__(256)
void k_gemm_h(const __half* __restrict__ A, const __half* __restrict__ Wt,
              const float* __restrict__ bc,
              __half* __restrict__ Ch, float* __restrict__ Cc,
              int M, int K, int NBF, int Ntot)
{
    constexpr int BN    = 16 * NT;
    constexpr int NPAIR = NT / 2;
    constexpr int TAIL  = NT & 1;
    __shared__ __align__(16) uint32_t As[4][128][12];
    __shared__ __align__(16) uint32_t Bs[4][BN][12];

    const int tid  = threadIdx.x;
    const int bm   = blockIdx.y * 128;
    const int bn   = blockIdx.x * BN;
    const int w    = tid >> 5, lane = tid & 31;
    const int wm   = w & 3,   wn   = w >> 2;
    const int g    = lane >> 2, t4 = lane & 3;

    const int crow = tid >> 1, ch = tid & 1;
    const bool aval = (bm + crow) < M;
    const __half* agp = A  + (size_t)(bm + crow) * K + ch * 8;
    const __half* bgp = Wt + (size_t)(bn + crow) * K + ch * 8;
    const bool bv = (tid < 2 * BN);

    uint32_t a_s = (uint32_t)__cvta_generic_to_shared(&As[0][crow][ch * 4]);
    uint32_t b_s = (uint32_t)__cvta_generic_to_shared(&Bs[0][crow][ch * 4]);
    constexpr uint32_t ASTRIDE = 128 * 12 * 4;
    constexpr uint32_t BSTRIDE = BN * 12 * 4;

    const int rm0 = wm * 32;
    const int cn0 = wn * NT * 8;

    const int arow = rm0 + ((lane >> 3) & 1) * 8 + (lane & 7);
    const int awrd = (lane >> 4) * 4;
    const uint32_t sA0 = (uint32_t)__cvta_generic_to_shared(&As[0][arow][awrd]);
    uint32_t sB[NPAIR + TAIL];
#pragma unroll
    for (int p = 0; p < NPAIR; p++) {
        int brow = cn0 + p * 16 + ((lane >> 4) & 1) * 8 + (lane & 7);
        int bwrd = ((lane >> 3) & 1) * 4;
        sB[p] = (uint32_t)__cvta_generic_to_shared(&Bs[0][brow][bwrd]);
    }
    if (TAIL) {
        int brow = cn0 + NPAIR * 16 + (lane & 7);
        int bwrd = ((lane >> 3) & 1) * 4;
        sB[NPAIR] = (uint32_t)__cvta_generic_to_shared(&Bs[0][brow][bwrd]);
    }

#define ISSUE(S, K0)                                                   \
    do {                                                               \
        cpa16(a_s + (S) * ASTRIDE, agp + (K0), aval);                  \
        if (bv) cpa16(b_s + (S) * BSTRIDE, bgp + (K0), true);          \
        asm volatile("cp.async.commit_group;");                        \
    } while (0)

    float acc[2][NT][4];
#pragma unroll
    for (int i = 0; i < 2; i++)
#pragma unroll
        for (int j = 0; j < NT; j++)
#pragma unroll
            for (int r = 0; r < 4; r++) acc[i][j][r] = 0.0f;

    // PDL: all setup above is independent of the producer's output; wait for
    // producer memory visibility just before the first dependent read.
    gdc_wait();

    const int kiter = K >> 4;
    ISSUE(0, 0);
    ISSUE(1, 16);
    ISSUE(2, 32);

    for (int it = 0; it < kiter; it++) {
        asm volatile("cp.async.wait_group 2;");
        __syncthreads();
        const uint32_t aoff = (uint32_t)(it & 3) * ASTRIDE;
        const uint32_t boff = (uint32_t)(it & 3) * BSTRIDE;
        {
            uint32_t af0[4], af1[4];
            ldsm4(af0[0], af0[1], af0[2], af0[3], sA0 + aoff);
            ldsm4(af1[0], af1[1], af1[2], af1[3], sA0 + aoff + 16 * 48);
            uint32_t bf[NT][2];
#pragma unroll
            for (int p = 0; p < NPAIR; p++)
                ldsm4(bf[2 * p][0], bf[2 * p][1], bf[2 * p + 1][0], bf[2 * p + 1][1],
                      sB[p] + boff);
            if (TAIL)
                ldsm2(bf[NT - 1][0], bf[NT - 1][1], sB[NPAIR] + boff);
#pragma unroll
            for (int j = 0; j < NT; j++) {
                mma16(acc[0][j], af0, bf[j]);
                mma16(acc[1][j], af1, bf[j]);
            }
        }
        if (it + 3 < kiter) ISSUE((it + 3) & 3, (it + 3) * 16);
        else asm volatile("cp.async.commit_group;");
    }
#undef ISSUE

    // bulk done — let the dependent kernel begin launching during our epilogue
    gdc_launch();

    // ---- epilogue ----
#pragma unroll
    for (int i = 0; i < 2; i++) {
        int r0 = bm + rm0 + i * 16 + g;
#pragma unroll
        for (int j = 0; j < NT; j++) {
            int col = bn + cn0 + j * 8 + 2 * t4;
            if (col >= Ntot) continue;
            if (col < NBF) {
                if (r0 < M) {
                    __half2 h = __floats2half2_rn(acc[i][j][0], acc[i][j][1]);
                    *reinterpret_cast<__half2*>(&Ch[(size_t)r0 * NBF + col]) = h;
                }
                if (r0 + 8 < M) {
                    __half2 h = __floats2half2_rn(acc[i][j][2], acc[i][j][3]);
                    *reinterpret_cast<__half2*>(&Ch[(size_t)(r0 + 8) * NBF + col]) = h;
                }
            } else {
                int cc = col - NBF;
                float b0 = bc[cc], b1 = bc[cc + 1];
                if (r0 < M) {
                    float2 v = make_float2(acc[i][j][0] + b0, acc[i][j][1] + b1);
                    *reinterpret_cast<float2*>(&Cc[(size_t)r0 * 96 + cc]) = v;
                }
                if (r0 + 8 < M) {
                    float2 v = make_float2(acc[i][j][2] + b0, acc[i][j][3] + b1);
                    *reinterpret_cast<float2*>(&Cc[(size_t)(r0 + 8) * 96 + cc]) = v;
                }
            }
        }
    }
}

// ---------------- fused aggregation + combine + bias (+relu / +log_softmax) --
__device__ __forceinline__ float4 h4f(uint2 u) {
    __half2 a = *reinterpret_cast<__half2*>(&u.x);
    __half2 b = *reinterpret_cast<__half2*>(&u.y);
    float2 fa = __half22float2(a), fb = __half22float2(b);
    return make_float4(fa.x, fa.y, fb.x, fb.y);
}

template<int NBF, int F, bool RELU, bool LSM>
__global__ __launch_bounds__(256)
void k_agg(const __half* __restrict__ linh, const float* __restrict__ linc,
           const float* __restrict__ bias, void* __restrict__ out_v, int n)
{
    constexpr int HF  = 8 * F;
    constexpr int NI  = HF / 32;
    constexpr int NH4 = NBF / 4;
    constexpr int C4  = (NH4 + 31) / 32;
    constexpr int UN  = (C4 == 1) ? 8 : 4;
    __shared__ float agg_s[8][3 * NBF];
    __shared__ float comb_s[8][96];

    int gw   = (blockIdx.x * 256 + threadIdx.x) >> 5;
    int lane = threadIdx.x & 31;
    int lw   = threadIdx.x >> 5;
    if (gw >= n) { gdc_wait(); gdc_launch(); return; }

    int s = g_off[gw];
    int deg = g_deg[gw];
    int e = s + deg;

    float4 vsym[C4], vsum[C4], vmax[C4];
#pragma unroll
    for (int q = 0; q < C4; q++) {
        vsym[q] = make_float4(0.f, 0.f, 0.f, 0.f);
        vsum[q] = make_float4(0.f, 0.f, 0.f, 0.f);
        vmax[q] = make_float4(-INFINITY, -INFINITY, -INFINITY, -INFINITY);
    }

    // PDL: wait for producer (GEMM writing linh/linc) before gathering.
    gdc_wait();

    int t = s;
    for (; t + UN <= e; t += UN) {
        int cc[UN]; float dd[UN]; const uint2* sp[UN];
#pragma unroll
        for (int u = 0; u < UN; u++) {
            cc[u] = g_adj[t + u];
            dd[u] = g_adjd[t + u];
            sp[u] = reinterpret_cast<const uint2*>(linh + (size_t)cc[u] * NBF);
        }
#pragma unroll
        for (int q = 0; q < C4; q++) {
            int i4 = lane + q * 32;
            if (C4 > 1 && i4 >= NH4) break;
            float4 vv[UN];
#pragma unroll
            for (int u = 0; u < UN; u++) vv[u] = h4f(sp[u][i4]);
#pragma unroll
            for (int u = 0; u < UN; u++) {
                vsym[q].x += dd[u] * vv[u].x; vsym[q].y += dd[u] * vv[u].y;
                vsym[q].z += dd[u] * vv[u].z; vsym[q].w += dd[u] * vv[u].w;
                vsum[q].x += vv[u].x; vsum[q].y += vv[u].y;
                vsum[q].z += vv[u].z; vsum[q].w += vv[u].w;
                vmax[q].x = fmaxf(vmax[q].x, vv[u].x);
                vmax[q].y = fmaxf(vmax[q].y, vv[u].y);
                vmax[q].z = fmaxf(vmax[q].z, vv[u].z);
                vmax[q].w = fmaxf(vmax[q].w, vv[u].w);
            }
        }
    }
    for (; t < e; t++) {
        int c0 = g_adj[t];
        float d0 = g_adjd[t];
        const uint2* s0 = reinterpret_cast<const uint2*>(linh + (size_t)c0 * NBF);
#pragma unroll
        for (int q = 0; q < C4; q++) {
            int i4 = lane + q * 32;
            if (C4 > 1 && i4 >= NH4) break;
            float4 v0 = h4f(s0[i4]);
            vsym[q].x += d0 * v0.x; vsym[q].y += d0 * v0.y;
            vsym[q].z += d0 * v0.z; vsym[q].w += d0 * v0.w;
            vsum[q].x += v0.x; vsum[q].y += v0.y;
            vsum[q].z += v0.z; vsum[q].w += v0.w;
            vmax[q].x = fmaxf(vmax[q].x, v0.x); vmax[q].y = fmaxf(vmax[q].y, v0.y);
            vmax[q].z = fmaxf(vmax[q].z, v0.z); vmax[q].w = fmaxf(vmax[q].w, v0.w);
        }
    }

    // bulk (gather) done — dependents may start launching
    gdc_launch();

    float dn   = g_dinv[gw];
    float invd = (deg > 0) ? (1.0f / (float)deg) : 0.0f;

    float4* arow0 = reinterpret_cast<float4*>(&agg_s[lw][0]);
    float4* arow1 = reinterpret_cast<float4*>(&agg_s[lw][NBF]);
    float4* arow2 = reinterpret_cast<float4*>(&agg_s[lw][2 * NBF]);
#pragma unroll
    for (int q = 0; q < C4; q++) {
        int i4 = lane + q * 32;
        if (C4 > 1 && i4 >= NH4) break;
        float4 sy = vsym[q];
        sy.x *= dn; sy.y *= dn; sy.z *= dn; sy.w *= dn;
        float4 me = vsum[q];
        me.x *= invd; me.y *= invd; me.z *= invd; me.w *= invd;
        float4 mx = vmax[q];
        if (deg == 0) mx = make_float4(0.f, 0.f, 0.f, 0.f);
        arow0[i4] = sy;
        arow1[i4] = me;
        arow2[i4] = mx;
    }

    const float* comb = linc + (size_t)gw * 96;
    comb_s[lw][lane]      = comb[lane];
    comb_s[lw][lane + 32] = comb[lane + 32];
    comb_s[lw][lane + 64] = comb[lane + 64];
    __syncwarp();

    float vals[NI];
#pragma unroll
    for (int i = 0; i < NI; i++) {
        int c = lane + i * 32;
        int h = c / F, f = c % F;
        float v = bias[c];
        const float* cb = &comb_s[lw][h * 12];
        const float* ag = &agg_s[lw][0];
#pragma unroll
        for (int k = 0; k < 12; k++) v = fmaf(cb[k], ag[k * F + f], v);
        if (RELU) v = fmaxf(v, 0.0f);
        vals[i] = v;
    }

    if (!LSM) {
        __half* out = (__half*)out_v;
#pragma unroll
        for (int i = 0; i < NI; i++)
            out[(size_t)gw * HF + lane + i * 32] = __float2half_rn(vals[i]);
    } else {
        float* out = (float*)out_v;
        float m = -INFINITY;
#pragma unroll
        for (int i = 0; i < NI; i++) {
            int c = lane + i * 32;
            m = fmaxf(m, (c < OUTT) ? vals[i] : -INFINITY);
        }
#pragma unroll
        for (int o = 16; o; o >>= 1) m = fmaxf(m, __shfl_xor_sync(0xffffffffu, m, o));
        float sum = 0.0f;
#pragma unroll
        for (int i = 0; i < NI; i++) {
            int c = lane + i * 32;
            if (c < OUTT) sum += expf(vals[i] - m);
        }
#pragma unroll
        for (int o = 16; o; o >>= 1) sum += __shfl_xor_sync(0xffffffffu, sum, o);
        float l = m + logf(sum);
#pragma unroll
        for (int i = 0; i < NI; i++) {
            int c = lane + i * 32;
            if (c < OUTT) out[(size_t)gw * OUTT + c] = vals[i] - l;
        }
    }
}

// ---------------- launch --------------------------------------------------------
extern "C" void kernel_launch(void* const* d_in, const int* in_sizes, int n_in,
                              void* d_out, int out_size)
{
    const float* x   = (const float*)d_in[0];
    const int*   ei  = (const int*)d_in[1];
    int N = in_sizes[0] / 128;
    int E = in_sizes[1] / 2;
    if (N > NMAX) N = NMAX;
    if (E > EMAX) E = EMAX;
    const int* row = ei;
    const int* col = ei + E;

    const float* Wb0 = (const float*)d_in[2];
    const float* Wc0 = (const float*)d_in[3];
    const float* bc0 = (const float*)d_in[4];
    const float* b0  = (const float*)d_in[5];
    const float* Wb1 = (const float*)d_in[6];
    const float* Wc1 = (const float*)d_in[7];
    const float* bc1 = (const float*)d_in[8];
    const float* b1  = (const float*)d_in[9];
    const float* Wb2 = (const float*)d_in[10];
    const float* Wc2 = (const float*)d_in[11];
    const float* bc2 = (const float*)d_in[12];
    const float* b2  = (const float*)d_in[13];

    __half* linh; float* linc; __half* xh; __half* hA; __half* hB;
    __half* wt0; __half* wt1; __half* wt2;
    cudaGetSymbolAddress((void**)&linh, g_linh);
    cudaGetSymbolAddress((void**)&linc, g_linc);
    cudaGetSymbolAddress((void**)&xh,   g_xh);
    cudaGetSymbolAddress((void**)&hA,   g_hA);
    cudaGetSymbolAddress((void**)&hB,   g_hB);
    cudaGetSymbolAddress((void**)&wt0,  g_wt0);
    cudaGetSymbolAddress((void**)&wt1,  g_wt1);
    cudaGetSymbolAddress((void**)&wt2,  g_wt2);

    const int T  = 256;
    const int gy = (N + 127) / 128;
    const int ab = (N + 7) / 8;
    const int n4 = N * 128 / 4;
    const int W12 = 224 * 256 + 288 * 256;
    const int XW0 = n4 + 224 * 128;

    // Streams/events created ONCE (first call is uncaptured) — no per-call
    // driver allocations, teardown baseline undisturbed. Deterministic DAG.
    static cudaStream_t s1 = nullptr, s2 = nullptr;
    static cudaEvent_t evRoot = nullptr, evCsr = nullptr, evW12 = nullptr;
    if (!s1) {
        cudaStreamCreateWithFlags(&s1, cudaStreamNonBlocking);
        cudaStreamCreateWithFlags(&s2, cudaStreamNonBlocking);
        cudaEventCreateWithFlags(&evRoot, cudaEventDisableTiming);
        cudaEventCreateWithFlags(&evCsr,  cudaEventDisableTiming);
        cudaEventCreateWithFlags(&evW12,  cudaEventDisableTiming);
    }

    cudaEventRecord(evRoot, 0);
    cudaStreamWaitEvent(s1, evRoot, 0);
    cudaStreamWaitEvent(s2, evRoot, 0);

    // s1: CSR build
    k_zero   <<<(N + T - 1) / T, T, 0, s1>>>(N);
    k_deg    <<<(E + T - 1) / T, T, 0, s1>>>(row, E);
    k_off    <<<(N + T - 1) / T, T, 0, s1>>>(N);
    k_scatter<<<(E + T - 1) / T, T, 0, s1>>>(row, col, E);
    cudaEventRecord(evCsr, s1);

    // s2: layer-1/2 weight converts
    k_cvt_w12<<<(W12 + T - 1) / T, T, 0, s2>>>(Wb1, Wc1, Wb2, Wc2, wt1, wt2);
    cudaEventRecord(evW12, s2);

    // PDL launch config for main-chain kernels (programmatic edge to the
    // immediately preceding kernel on this stream; event edges stay full).
    cudaLaunchConfig_t cfg = {};
    cfg.stream = 0;
    cudaLaunchAttribute attrs[1];
    attrs[0].id = cudaLaunchAttributeProgrammaticStreamSerialization;
    attrs[0].val.programmaticStreamSerializationAllowed = 1;
    cfg.attrs = attrs;
    cfg.numAttrs = 1;

    // main: fused x+w0 convert, then gemm0 (PDL on the convert)
    k_cvt_xw0<<<(XW0 + T - 1) / T, T>>>(x, (__half2*)xh, n4, Wb0, Wc0, wt0);

    cfg.gridDim = dim3(2, gy); cfg.blockDim = dim3(256);
    cudaLaunchKernelEx(&cfg, k_gemm_h<7>, (const __half*)xh, (const __half*)wt0,
                       bc0, linh, linc, N, 128, 128, 224);

    // joins (full edges)
    cudaStreamWaitEvent(0, evCsr, 0);
    cudaStreamWaitEvent(0, evW12, 0);

    cfg.gridDim = dim3(ab); cfg.blockDim = dim3(256);
    cudaLaunchKernelEx(&cfg, k_agg<128, 32, true, false>,
                       (const __half*)linh, (const float*)linc, b0, (void*)hA, N);

    cfg.gridDim = dim3(2, gy);
    cudaLaunchKernelEx(&cfg, k_gemm_h<7>, (const __half*)hA, (const __half*)wt1,
                       bc1, linh, linc, N, 256, 128, 224);

    cfg.gridDim = dim3(ab);
    cudaLaunchKernelEx(&cfg, k_agg<128, 32, true, false>,
                       (const __half*)linh, (const float*)linc, b1, (void*)hB, N);

    cfg.gridDim = dim3(3, gy);
    cudaLaunchKernelEx(&cfg, k_gemm_h<6>, (const __half*)hB, (const __half*)wt2,
                       bc2, linh, linc, N, 256, 176, 272);

    cfg.gridDim = dim3(ab);
    cudaLaunchKernelEx(&cfg, k_agg<176, 44, false, true>,
                       (const __half*)linh, (const float*)linc, b2, d_out, N);
}